// round 2
// baseline (speedup 1.0000x reference)
#include <cuda_runtime.h>
#include <cuda_bf16.h>
#include <cstdint>
#include <math.h>

#define N_NODES 40000
#define N_EDGES 160000
#define DIN 64
#define D 32
#define EIN 16
#define EH 128
#define STEPS 3
#define EPS_BN 1e-5f

// ---------------- device scratch (no allocation allowed) ----------------
__device__ float g_h[N_NODES * D];                  // node features / GRU hidden
__device__ float g_eh[N_EDGES * EH];                // edge hidden (82 MB)
__device__ uint32_t g_theta[(size_t)N_EDGES * 512]; // per-edge mats, bf16 pairs (327 MB)
__device__ float g_agg[N_NODES * D];                // scatter-add accumulator

// ---------------- helpers ----------------
__device__ __forceinline__ float cvt_tf32(float x) {
    uint32_t u;
    asm("cvt.rna.tf32.f32 %0, %1;" : "=r"(u) : "f"(x));
    return __uint_as_float(u);
}

__device__ __forceinline__ void mma_tf32_16x8x8(float c[4], const uint32_t a[4],
                                                uint32_t b0, uint32_t b1) {
    asm volatile(
        "mma.sync.aligned.m16n8k8.row.col.f32.tf32.tf32.f32 "
        "{%0,%1,%2,%3}, {%4,%5,%6,%7}, {%8,%9}, {%0,%1,%2,%3};"
        : "+f"(c[0]), "+f"(c[1]), "+f"(c[2]), "+f"(c[3])
        : "r"(a[0]), "r"(a[1]), "r"(a[2]), "r"(a[3]), "r"(b0), "r"(b1));
}

// ---------------- K1: h = relu(bn(x @ proj_W + proj_b)); also zero g_agg ----
__global__ void __launch_bounds__(256) k_proj(const float* __restrict__ x,
                                              const float* __restrict__ W,
                                              const float* __restrict__ b,
                                              const float* __restrict__ g,
                                              const float* __restrict__ bb) {
    __shared__ float Ws[DIN * D]; // [64][32]
    int tid = threadIdx.x;
    for (int i = tid; i < DIN * D; i += 256) Ws[i] = W[i];
    __syncthreads();
    int lane = tid & 31;
    int node = blockIdx.x * 8 + (tid >> 5);
    if (node >= N_NODES) return;
    float x0 = x[node * DIN + lane];
    float x1 = x[node * DIN + 32 + lane];
    float acc = 0.f;
#pragma unroll
    for (int i = 0; i < 32; i++) {
        acc = fmaf(__shfl_sync(0xffffffffu, x0, i), Ws[i * D + lane], acc);
        acc = fmaf(__shfl_sync(0xffffffffu, x1, i), Ws[(32 + i) * D + lane], acc);
    }
    float s = g[lane] * rsqrtf(1.f + EPS_BN);
    float v = (acc + b[lane]) * s + bb[lane];
    g_h[node * D + lane] = fmaxf(v, 0.f);
    g_agg[node * D + lane] = 0.f;
}

// ---------------- K2: eh = relu(bn(edge_attr @ eW1 + eb1)) ----------------
__global__ void __launch_bounds__(256) k_edgehidden(const float* __restrict__ ea,
                                                    const float* __restrict__ W1,
                                                    const float* __restrict__ b1,
                                                    const float* __restrict__ g,
                                                    const float* __restrict__ bb) {
    __shared__ float W1s[EIN * EH]; // [16][128]
    __shared__ float eas[2][EIN];
    int tid = threadIdx.x;
    for (int i = tid; i < EIN * EH; i += 256) W1s[i] = W1[i];
    int e0 = blockIdx.x * 2;
    if (tid < 32) eas[tid >> 4][tid & 15] = ea[e0 * EIN + tid];
    __syncthreads();
    int el = tid >> 7;       // 0..1
    int k = tid & 127;       // 0..127
    int e = e0 + el;
    float acc = 0.f;
#pragma unroll
    for (int i = 0; i < EIN; i++) acc = fmaf(eas[el][i], W1s[i * EH + k], acc);
    float s = g[k] * rsqrtf(1.f + EPS_BN);
    float v = (acc + b1[k]) * s + bb[k];
    g_eh[(size_t)e * EH + k] = fmaxf(v, 0.f);
}

// ---------------- K3: theta = eh @ eW2 + eb2 (tf32 MMA, bf16 output) -------
// M=160000, N=1024, K=128. Block tile 128x128, K fully resident in smem.
// 256 threads = 8 warps (4 m x 2 n), warp tile 32x64.
#define AS_LD 132
#define BS_LD 136
#define GEMM_SMEM ((128 * AS_LD + 128 * BS_LD) * 4)

__global__ void __launch_bounds__(256) k_theta(const float* __restrict__ eW2,
                                               const float* __restrict__ eb2) {
    extern __shared__ float smem[];
    float* As = smem;               // [128][AS_LD]
    float* Bs = smem + 128 * AS_LD; // [128][BS_LD]
    const int tid = threadIdx.x;
    const int m0 = blockIdx.y * 128;
    const int n0 = blockIdx.x * 128;

    {
        int r = tid >> 5;
        int c4 = (tid & 31) * 4;
#pragma unroll
        for (int it = 0; it < 16; it++) {
            int row = r + it * 8;
            float4 v = *reinterpret_cast<const float4*>(&g_eh[(size_t)(m0 + row) * EH + c4]);
            v.x = cvt_tf32(v.x); v.y = cvt_tf32(v.y); v.z = cvt_tf32(v.z); v.w = cvt_tf32(v.w);
            *reinterpret_cast<float4*>(&As[row * AS_LD + c4]) = v;
        }
#pragma unroll
        for (int it = 0; it < 16; it++) {
            int row = r + it * 8; // k
            float4 v = *reinterpret_cast<const float4*>(&eW2[(size_t)row * 1024 + n0 + c4]);
            v.x = cvt_tf32(v.x); v.y = cvt_tf32(v.y); v.z = cvt_tf32(v.z); v.w = cvt_tf32(v.w);
            *reinterpret_cast<float4*>(&Bs[row * BS_LD + c4]) = v;
        }
    }
    __syncthreads();

    const int warp = tid >> 5, lane = tid & 31;
    const int wm = (warp & 3) * 32;
    const int wn = (warp >> 2) * 64;
    const int lq = lane >> 2;  // 0..7
    const int lr = lane & 3;   // 0..3

    float c[2][8][4];
#pragma unroll
    for (int mt = 0; mt < 2; mt++)
#pragma unroll
        for (int nt = 0; nt < 8; nt++)
#pragma unroll
            for (int i = 0; i < 4; i++) c[mt][nt][i] = 0.f;

#pragma unroll
    for (int ks = 0; ks < 16; ks++) {
        int k0 = ks * 8;
        uint32_t a[2][4];
#pragma unroll
        for (int mt = 0; mt < 2; mt++) {
            int row = wm + mt * 16 + lq;
            int col = k0 + lr;
            a[mt][0] = __float_as_uint(As[row * AS_LD + col]);
            a[mt][1] = __float_as_uint(As[(row + 8) * AS_LD + col]);
            a[mt][2] = __float_as_uint(As[row * AS_LD + col + 4]);
            a[mt][3] = __float_as_uint(As[(row + 8) * AS_LD + col + 4]);
        }
#pragma unroll
        for (int nt = 0; nt < 8; nt++) {
            int colB = wn + nt * 8 + lq;
            uint32_t b0 = __float_as_uint(Bs[(k0 + lr) * BS_LD + colB]);
            uint32_t b1 = __float_as_uint(Bs[(k0 + 4 + lr) * BS_LD + colB]);
            mma_tf32_16x8x8(c[0][nt], a[0], b0, b1);
            mma_tf32_16x8x8(c[1][nt], a[1], b0, b1);
        }
    }

    // epilogue: + eb2, pack bf16 pairs, store 4B per fragment-row
#pragma unroll
    for (int mt = 0; mt < 2; mt++) {
#pragma unroll
        for (int nt = 0; nt < 8; nt++) {
            int row = m0 + wm + mt * 16 + lq;
            int col = n0 + wn + nt * 8 + lr * 2; // even
            float bv0 = eb2[col], bv1 = eb2[col + 1];
            __nv_bfloat162 p0 = __floats2bfloat162_rn(c[mt][nt][0] + bv0, c[mt][nt][1] + bv1);
            __nv_bfloat162 p1 = __floats2bfloat162_rn(c[mt][nt][2] + bv0, c[mt][nt][3] + bv1);
            g_theta[((size_t)row * 1024 + col) >> 1] = *reinterpret_cast<uint32_t*>(&p0);
            g_theta[((size_t)(row + 8) * 1024 + col) >> 1] = *reinterpret_cast<uint32_t*>(&p1);
        }
    }
}

// ---------------- K5: msg = h[src] @ theta_e ; atomic scatter to agg[dst] ----
// warp/edge; lane quarter q handles rows q,q+4,..,q+28; 4 cols per lane via LDG.64
__global__ void __launch_bounds__(256) k_msg(const int* __restrict__ ei) {
    int gw = (blockIdx.x * blockDim.x + threadIdx.x) >> 5;
    if (gw >= N_EDGES) return;
    int lane = threadIdx.x & 31;
    int src = __ldg(&ei[gw]);
    int dst = __ldg(&ei[N_EDGES + gw]);
    float hv = g_h[src * D + lane];
    const uint2* th = reinterpret_cast<const uint2*>(g_theta + (size_t)gw * 512);
    const int q = lane >> 3;        // 0..3 (row group)
    const int c8 = lane & 7;        // col-quad index; cols 4*c8 .. 4*c8+3
    float a0 = 0.f, a1 = 0.f, a2 = 0.f, a3 = 0.f;
#pragma unroll
    for (int it = 0; it < 8; it++) {
        int r = it * 4 + q;
        uint2 u = th[r * 8 + c8];   // 4 bf16 = cols 4*c8..+3 of row r
        float hr = __shfl_sync(0xffffffffu, hv, r);
        float2 f01 = __bfloat1622float2(*reinterpret_cast<const __nv_bfloat162*>(&u.x));
        float2 f23 = __bfloat1622float2(*reinterpret_cast<const __nv_bfloat162*>(&u.y));
        a0 = fmaf(hr, f01.x, a0);
        a1 = fmaf(hr, f01.y, a1);
        a2 = fmaf(hr, f23.x, a2);
        a3 = fmaf(hr, f23.y, a3);
    }
    // combine the 4 row-groups (lanes l, l+8, l+16, l+24 share columns)
    a0 += __shfl_xor_sync(0xffffffffu, a0, 8);
    a1 += __shfl_xor_sync(0xffffffffu, a1, 8);
    a2 += __shfl_xor_sync(0xffffffffu, a2, 8);
    a3 += __shfl_xor_sync(0xffffffffu, a3, 8);
    a0 += __shfl_xor_sync(0xffffffffu, a0, 16);
    a1 += __shfl_xor_sync(0xffffffffu, a1, 16);
    a2 += __shfl_xor_sync(0xffffffffu, a2, 16);
    a3 += __shfl_xor_sync(0xffffffffu, a3, 16);
    if (lane < 8) {
        float* dp = &g_agg[dst * D + c8 * 4];
        atomicAdd(dp + 0, a0);
        atomicAdd(dp + 1, a1);
        atomicAdd(dp + 2, a2);
        atomicAdd(dp + 3, a3);
    }
}

// ---------------- K6: conv + relu + GRU cell, in-place; resets agg ----------
__global__ void __launch_bounds__(256) k_update(const float* __restrict__ root,
                                                const float* __restrict__ cb,
                                                const float* __restrict__ W_ih,
                                                const float* __restrict__ W_hh,
                                                const float* __restrict__ b_ih,
                                                const float* __restrict__ b_hh,
                                                float* __restrict__ out,
                                                int write_out) {
    __shared__ float s_wih[D * 96]; // transposed [i][j]
    __shared__ float s_whh[D * 96];
    __shared__ float s_root[D * D];
    __shared__ float s_bih[96], s_bhh[96], s_cb[D];
    int tid = threadIdx.x;
    for (int idx = tid; idx < 96 * D; idx += 256) {
        int j = idx / D, i = idx % D;
        s_wih[i * 96 + j] = W_ih[idx];
        s_whh[i * 96 + j] = W_hh[idx];
    }
    for (int idx = tid; idx < D * D; idx += 256) s_root[idx] = root[idx];
    if (tid < 96) { s_bih[tid] = b_ih[tid]; s_bhh[tid] = b_hh[tid]; }
    if (tid < D) s_cb[tid] = cb[tid];
    __syncthreads();

    int lane = tid & 31;
    int v = blockIdx.x * 8 + (tid >> 5);
    if (v >= N_NODES) return;

    float hv = g_h[v * D + lane];
    float conv = g_agg[v * D + lane] + s_cb[lane];
    g_agg[v * D + lane] = 0.f; // reset for next step
#pragma unroll
    for (int i = 0; i < 32; i++)
        conv = fmaf(__shfl_sync(0xffffffffu, hv, i), s_root[i * D + lane], conv);
    float m = fmaxf(conv, 0.f);

    float gr = s_bih[lane], gz = s_bih[32 + lane], gn = s_bih[64 + lane];
    float hr = s_bhh[lane], hz = s_bhh[32 + lane], hn = s_bhh[64 + lane];
#pragma unroll
    for (int i = 0; i < 32; i++) {
        float mi = __shfl_sync(0xffffffffu, m, i);
        float hi = __shfl_sync(0xffffffffu, hv, i);
        const float* wi = &s_wih[i * 96];
        const float* wh = &s_whh[i * 96];
        gr = fmaf(mi, wi[lane], gr);
        gz = fmaf(mi, wi[32 + lane], gz);
        gn = fmaf(mi, wi[64 + lane], gn);
        hr = fmaf(hi, wh[lane], hr);
        hz = fmaf(hi, wh[32 + lane], hz);
        hn = fmaf(hi, wh[64 + lane], hn);
    }
    float r = 1.f / (1.f + expf(-(gr + hr)));
    float z = 1.f / (1.f + expf(-(gz + hz)));
    float n = tanhf(gn + r * hn);
    float hnew = (1.f - z) * n + z * hv;
    g_h[v * D + lane] = hnew;
    if (write_out) out[v * D + lane] = hnew;
}

// ---------------- launch ----------------
extern "C" void kernel_launch(void* const* d_in, const int* in_sizes, int n_in,
                              void* d_out, int out_size) {
    (void)in_sizes; (void)n_in; (void)out_size;
    const float* x        = (const float*)d_in[0];
    const int*   ei       = (const int*)d_in[1];
    const float* ea       = (const float*)d_in[2];
    const float* proj_W   = (const float*)d_in[3];
    const float* proj_b   = (const float*)d_in[4];
    const float* bn1_g    = (const float*)d_in[5];
    const float* bn1_b    = (const float*)d_in[6];
    const float* eW1      = (const float*)d_in[7];
    const float* eb1      = (const float*)d_in[8];
    const float* bn2_g    = (const float*)d_in[9];
    const float* bn2_b    = (const float*)d_in[10];
    const float* eW2      = (const float*)d_in[11];
    const float* eb2      = (const float*)d_in[12];
    const float* root     = (const float*)d_in[13];
    const float* cb       = (const float*)d_in[14];
    const float* W_ih     = (const float*)d_in[15];
    const float* W_hh     = (const float*)d_in[16];
    const float* b_ih     = (const float*)d_in[17];
    const float* b_hh     = (const float*)d_in[18];
    float* out = (float*)d_out;

    k_proj<<<N_NODES / 8, 256>>>(x, proj_W, proj_b, bn1_g, bn1_b);
    k_edgehidden<<<N_EDGES / 2, 256>>>(ea, eW1, eb1, bn2_g, bn2_b);

    static int smem_set = 0;
    if (!smem_set) {
        cudaFuncSetAttribute(k_theta, cudaFuncAttributeMaxDynamicSharedMemorySize, GEMM_SMEM);
        smem_set = 1;
    }
    dim3 tgrid(1024 / 128, N_EDGES / 128); // (8, 1250)
    k_theta<<<tgrid, 256, GEMM_SMEM>>>(eW2, eb2);

    for (int s = 0; s < STEPS; s++) {
        k_msg<<<(N_EDGES * 32) / 256, 256>>>(ei);
        k_update<<<N_NODES / 8, 256>>>(root, cb, W_ih, W_hh, b_ih, b_hh,
                                       out, s == STEPS - 1 ? 1 : 0);
    }
}

// round 4
// speedup vs baseline: 1.8725x; 1.8725x over previous
#include <cuda_runtime.h>
#include <cuda_fp16.h>
#include <cstdint>
#include <math.h>

#define N_NODES 40000
#define N_EDGES 160000
#define DIN 64
#define D 32
#define EIN 16
#define EH 128
#define STEPS 3
#define EPS_BN 1e-5f

// ---------------- device scratch (no allocation allowed) ----------------
__device__ float g_h[N_NODES * D];                  // node features / GRU hidden
__device__ float g_eh[N_EDGES * EH];                // edge hidden (82 MB)
__device__ uint32_t g_theta[(size_t)N_EDGES * 512]; // per-edge mats, fp16 pairs (327 MB)
__device__ float g_agg[N_NODES * D];                // scatter-add accumulator
__device__ __half g_Bh[1024 * 128];                 // fp16 W2^T, [n][k] row-major (256 KB)

// ---------------- fp16 MMA helper (sm_103-safe, no 'a' features) -----------
__device__ __forceinline__ void mma_f16_16x8x16(float c[4], const uint32_t a[4],
                                                uint32_t b0, uint32_t b1) {
    asm volatile(
        "mma.sync.aligned.m16n8k16.row.col.f32.f16.f16.f32 "
        "{%0,%1,%2,%3}, {%4,%5,%6,%7}, {%8,%9}, {%0,%1,%2,%3};"
        : "+f"(c[0]), "+f"(c[1]), "+f"(c[2]), "+f"(c[3])
        : "r"(a[0]), "r"(a[1]), "r"(a[2]), "r"(a[3]), "r"(b0), "r"(b1));
}

// ---------------- K0: fp16 B = W2^T image, [n][k] row-major -----------------
__global__ void __launch_bounds__(256) k_prepB(const float* __restrict__ eW2) {
    int i = blockIdx.x * 256 + threadIdx.x; // 131072 total
    int k = i >> 10;       // 0..127 (eW2 row)
    int n = i & 1023;      // 0..1023 (coalesced read)
    g_Bh[n * 128 + k] = __float2half_rn(eW2[k * 1024 + n]);
}

// ---------------- K1: h = relu(bn(x @ proj_W + proj_b)); also zero g_agg ----
__global__ void __launch_bounds__(256) k_proj(const float* __restrict__ x,
                                              const float* __restrict__ W,
                                              const float* __restrict__ b,
                                              const float* __restrict__ g,
                                              const float* __restrict__ bb) {
    __shared__ float Ws[DIN * D];
    int tid = threadIdx.x;
    for (int i = tid; i < DIN * D; i += 256) Ws[i] = W[i];
    __syncthreads();
    int lane = tid & 31;
    int node = blockIdx.x * 8 + (tid >> 5);
    if (node >= N_NODES) return;
    float x0 = x[node * DIN + lane];
    float x1 = x[node * DIN + 32 + lane];
    float acc = 0.f;
#pragma unroll
    for (int i = 0; i < 32; i++) {
        acc = fmaf(__shfl_sync(0xffffffffu, x0, i), Ws[i * D + lane], acc);
        acc = fmaf(__shfl_sync(0xffffffffu, x1, i), Ws[(32 + i) * D + lane], acc);
    }
    float s = g[lane] * rsqrtf(1.f + EPS_BN);
    float v = (acc + b[lane]) * s + bb[lane];
    g_h[node * D + lane] = fmaxf(v, 0.f);
    g_agg[node * D + lane] = 0.f;
}

// ---------------- K2: eh = relu(bn(edge_attr @ eW1 + eb1)) ----------------
__global__ void __launch_bounds__(256) k_edgehidden(const float* __restrict__ ea,
                                                    const float* __restrict__ W1,
                                                    const float* __restrict__ b1,
                                                    const float* __restrict__ g,
                                                    const float* __restrict__ bb) {
    __shared__ float W1s[EIN * EH];
    __shared__ float eas[2][EIN];
    int tid = threadIdx.x;
    for (int i = tid; i < EIN * EH; i += 256) W1s[i] = W1[i];
    int e0 = blockIdx.x * 2;
    if (tid < 32) eas[tid >> 4][tid & 15] = ea[e0 * EIN + tid];
    __syncthreads();
    int el = tid >> 7;
    int k = tid & 127;
    int e = e0 + el;
    float acc = 0.f;
#pragma unroll
    for (int i = 0; i < EIN; i++) acc = fmaf(eas[el][i], W1s[i * EH + k], acc);
    float s = g[k] * rsqrtf(1.f + EPS_BN);
    float v = (acc + b1[k]) * s + bb[k];
    g_eh[(size_t)e * EH + k] = fmaxf(v, 0.f);
}

// ---------------- K3: theta = eh @ eW2 + eb2 (fp16 m16n8k16 MMA) ------------
// Block: M=128 edges x full N=1024 (8 panels of 128). K=128 resident in smem.
// smem (dynamic): As half[128][136] | Bs half[128][136] | bias fp32[1024]
#define A_LDH 136
#define B_LDH 136
#define TH_AS 0
#define TH_BS (128 * A_LDH * 2)            // 34816
#define TH_BIAS (TH_BS + 128 * B_LDH * 2)  // 69632
#define TH_SMEM_TOTAL (TH_BIAS + 4096)     // 73728

__global__ void __launch_bounds__(256, 2) k_theta(const float* __restrict__ eb2,
                                                  int mblk0) {
    extern __shared__ char smem[];
    __half* As = reinterpret_cast<__half*>(smem + TH_AS);
    __half* Bs = reinterpret_cast<__half*>(smem + TH_BS);
    float* biass = reinterpret_cast<float*>(smem + TH_BIAS);
    const int tid = threadIdx.x, warp = tid >> 5, lane = tid & 31;
    const int m0 = (mblk0 + blockIdx.x) * 128;

    for (int i = tid; i < 1024; i += 256) biass[i] = eb2[i];

    // A tile: 128x128 fp32 -> fp16 into padded smem
#pragma unroll
    for (int it = 0; it < 16; it++) {
        int idx = it * 256 + tid;
        int row = idx >> 5;
        int c4 = (idx & 31) << 2;
        float4 v = *reinterpret_cast<const float4*>(&g_eh[(size_t)(m0 + row) * EH + c4]);
        __half2 p0 = __floats2half2_rn(v.x, v.y);
        __half2 p1 = __floats2half2_rn(v.z, v.w);
        uint2 u = make_uint2(*reinterpret_cast<uint32_t*>(&p0),
                             *reinterpret_cast<uint32_t*>(&p1));
        *reinterpret_cast<uint2*>(&As[row * A_LDH + c4]) = u;
    }

    // B panel 0
    {
        const uint4* src = reinterpret_cast<const uint4*>(g_Bh);
#pragma unroll
        for (int it = 0; it < 8; it++) {
            int idx = it * 256 + tid;       // 2048 uint4 = 32KB
            int row = idx >> 4, q = idx & 15;
            *reinterpret_cast<uint4*>(&Bs[row * B_LDH + q * 8]) = src[idx];
        }
    }
    __syncthreads();

    const int wm = (warp & 3) * 32;
    const int wn = (warp >> 2) * 64;
    const int lq = lane >> 2;
    const int lr = lane & 3;

    for (int p = 0; p < 8; p++) {
        float c[2][8][4];
#pragma unroll
        for (int mt = 0; mt < 2; mt++)
#pragma unroll
            for (int nt = 0; nt < 8; nt++)
#pragma unroll
                for (int i = 0; i < 4; i++) c[mt][nt][i] = 0.f;

#pragma unroll
        for (int ks = 0; ks < 8; ks++) {
            int k0 = ks * 16;
            uint32_t a[2][4];
#pragma unroll
            for (int mt = 0; mt < 2; mt++) {
                int r = wm + mt * 16 + lq;
                a[mt][0] = *reinterpret_cast<const uint32_t*>(&As[r * A_LDH + k0 + lr * 2]);
                a[mt][1] = *reinterpret_cast<const uint32_t*>(&As[(r + 8) * A_LDH + k0 + lr * 2]);
                a[mt][2] = *reinterpret_cast<const uint32_t*>(&As[r * A_LDH + k0 + 8 + lr * 2]);
                a[mt][3] = *reinterpret_cast<const uint32_t*>(&As[(r + 8) * A_LDH + k0 + 8 + lr * 2]);
            }
#pragma unroll
            for (int nt = 0; nt < 8; nt++) {
                int n = wn + nt * 8 + lq;
                uint32_t b0 = *reinterpret_cast<const uint32_t*>(&Bs[n * B_LDH + k0 + lr * 2]);
                uint32_t b1 = *reinterpret_cast<const uint32_t*>(&Bs[n * B_LDH + k0 + 8 + lr * 2]);
                mma_f16_16x8x16(c[0][nt], a[0], b0, b1);
                mma_f16_16x8x16(c[1][nt], a[1], b0, b1);
            }
        }
        __syncthreads(); // all MMA reads of Bs complete

        // overlap: load next B panel (smem) while epilogue runs (regs+gmem only)
        if (p < 7) {
            const uint4* src = reinterpret_cast<const uint4*>(g_Bh + (size_t)(p + 1) * 128 * 128);
#pragma unroll
            for (int it = 0; it < 8; it++) {
                int idx = it * 256 + tid;
                int row = idx >> 4, q = idx & 15;
                *reinterpret_cast<uint4*>(&Bs[row * B_LDH + q * 8]) = src[idx];
            }
        }

        // epilogue: + bias, pack fp16 pairs, store
#pragma unroll
        for (int mt = 0; mt < 2; mt++) {
#pragma unroll
            for (int nt = 0; nt < 8; nt++) {
                int row = m0 + wm + mt * 16 + lq;
                int col = p * 128 + wn + nt * 8 + lr * 2;
                float bv0 = biass[col], bv1 = biass[col + 1];
                __half2 p0 = __floats2half2_rn(c[mt][nt][0] + bv0, c[mt][nt][1] + bv1);
                __half2 p1 = __floats2half2_rn(c[mt][nt][2] + bv0, c[mt][nt][3] + bv1);
                g_theta[((size_t)row * 1024 + col) >> 1] = *reinterpret_cast<uint32_t*>(&p0);
                g_theta[((size_t)(row + 8) * 1024 + col) >> 1] = *reinterpret_cast<uint32_t*>(&p1);
            }
        }
        __syncthreads(); // next panel's Bs writes visible before next compute
    }
}

// ---------------- K5: msg = h[src] @ theta_e ; atomic scatter to agg[dst] ----
__global__ void __launch_bounds__(256) k_msg(const int* __restrict__ ei) {
    int gw = (blockIdx.x * blockDim.x + threadIdx.x) >> 5;
    if (gw >= N_EDGES) return;
    int lane = threadIdx.x & 31;
    int src = __ldg(&ei[gw]);
    int dst = __ldg(&ei[N_EDGES + gw]);
    float hv = g_h[src * D + lane];
    const uint2* th = reinterpret_cast<const uint2*>(g_theta + (size_t)gw * 512);
    const int q = lane >> 3;
    const int c8 = lane & 7;
    float a0 = 0.f, a1 = 0.f, a2 = 0.f, a3 = 0.f;
#pragma unroll
    for (int it = 0; it < 8; it++) {
        int r = it * 4 + q;
        uint2 u = th[r * 8 + c8];
        float hr = __shfl_sync(0xffffffffu, hv, r);
        float2 f01 = __half22float2(*reinterpret_cast<const __half2*>(&u.x));
        float2 f23 = __half22float2(*reinterpret_cast<const __half2*>(&u.y));
        a0 = fmaf(hr, f01.x, a0);
        a1 = fmaf(hr, f01.y, a1);
        a2 = fmaf(hr, f23.x, a2);
        a3 = fmaf(hr, f23.y, a3);
    }
    a0 += __shfl_xor_sync(0xffffffffu, a0, 8);
    a1 += __shfl_xor_sync(0xffffffffu, a1, 8);
    a2 += __shfl_xor_sync(0xffffffffu, a2, 8);
    a3 += __shfl_xor_sync(0xffffffffu, a3, 8);
    a0 += __shfl_xor_sync(0xffffffffu, a0, 16);
    a1 += __shfl_xor_sync(0xffffffffu, a1, 16);
    a2 += __shfl_xor_sync(0xffffffffu, a2, 16);
    a3 += __shfl_xor_sync(0xffffffffu, a3, 16);
    if (lane < 8) {
        float* dp = &g_agg[dst * D + c8 * 4];
        atomicAdd(dp + 0, a0);
        atomicAdd(dp + 1, a1);
        atomicAdd(dp + 2, a2);
        atomicAdd(dp + 3, a3);
    }
}

// ---------------- K6: conv + relu + GRU cell, in-place; resets agg ----------
__global__ void __launch_bounds__(256) k_update(const float* __restrict__ root,
                                                const float* __restrict__ cb,
                                                const float* __restrict__ W_ih,
                                                const float* __restrict__ W_hh,
                                                const float* __restrict__ b_ih,
                                                const float* __restrict__ b_hh,
                                                float* __restrict__ out,
                                                int write_out) {
    __shared__ float s_wih[D * 96];
    __shared__ float s_whh[D * 96];
    __shared__ float s_root[D * D];
    __shared__ float s_bih[96], s_bhh[96], s_cb[D];
    int tid = threadIdx.x;
    for (int idx = tid; idx < 96 * D; idx += 256) {
        int j = idx / D, i = idx % D;
        s_wih[i * 96 + j] = W_ih[idx];
        s_whh[i * 96 + j] = W_hh[idx];
    }
    for (int idx = tid; idx < D * D; idx += 256) s_root[idx] = root[idx];
    if (tid < 96) { s_bih[tid] = b_ih[tid]; s_bhh[tid] = b_hh[tid]; }
    if (tid < D) s_cb[tid] = cb[tid];
    __syncthreads();

    int lane = tid & 31;
    int v = blockIdx.x * 8 + (tid >> 5);
    if (v >= N_NODES) return;

    float hv = g_h[v * D + lane];
    float conv = g_agg[v * D + lane] + s_cb[lane];
    g_agg[v * D + lane] = 0.f;
#pragma unroll
    for (int i = 0; i < 32; i++)
        conv = fmaf(__shfl_sync(0xffffffffu, hv, i), s_root[i * D + lane], conv);
    float m = fmaxf(conv, 0.f);

    float gr = s_bih[lane], gz = s_bih[32 + lane], gn = s_bih[64 + lane];
    float hr = s_bhh[lane], hz = s_bhh[32 + lane], hn = s_bhh[64 + lane];
#pragma unroll
    for (int i = 0; i < 32; i++) {
        float mi = __shfl_sync(0xffffffffu, m, i);
        float hi = __shfl_sync(0xffffffffu, hv, i);
        const float* wi = &s_wih[i * 96];
        const float* wh = &s_whh[i * 96];
        gr = fmaf(mi, wi[lane], gr);
        gz = fmaf(mi, wi[32 + lane], gz);
        gn = fmaf(mi, wi[64 + lane], gn);
        hr = fmaf(hi, wh[lane], hr);
        hz = fmaf(hi, wh[32 + lane], hz);
        hn = fmaf(hi, wh[64 + lane], hn);
    }
    float r = 1.f / (1.f + expf(-(gr + hr)));
    float z = 1.f / (1.f + expf(-(gz + hz)));
    float n = tanhf(gn + r * hn);
    float hnew = (1.f - z) * n + z * hv;
    g_h[v * D + lane] = hnew;
    if (write_out) out[v * D + lane] = hnew;
}

// ---------------- launch ----------------
extern "C" void kernel_launch(void* const* d_in, const int* in_sizes, int n_in,
                              void* d_out, int out_size) {
    (void)in_sizes; (void)n_in; (void)out_size;
    const float* x        = (const float*)d_in[0];
    const int*   ei       = (const int*)d_in[1];
    const float* ea       = (const float*)d_in[2];
    const float* proj_W   = (const float*)d_in[3];
    const float* proj_b   = (const float*)d_in[4];
    const float* bn1_g    = (const float*)d_in[5];
    const float* bn1_b    = (const float*)d_in[6];
    const float* eW1      = (const float*)d_in[7];
    const float* eb1      = (const float*)d_in[8];
    const float* bn2_g    = (const float*)d_in[9];
    const float* bn2_b    = (const float*)d_in[10];
    const float* eW2      = (const float*)d_in[11];
    const float* eb2      = (const float*)d_in[12];
    const float* root     = (const float*)d_in[13];
    const float* cb       = (const float*)d_in[14];
    const float* W_ih     = (const float*)d_in[15];
    const float* W_hh     = (const float*)d_in[16];
    const float* b_ih     = (const float*)d_in[17];
    const float* b_hh     = (const float*)d_in[18];
    float* out = (float*)d_out;

    static int attr_set = 0;
    if (!attr_set) {
        cudaFuncSetAttribute(k_theta, cudaFuncAttributeMaxDynamicSharedMemorySize,
                             TH_SMEM_TOTAL);
        attr_set = 1;
    }

    k_prepB<<<512, 256>>>(eW2);                                      // 1
    k_proj<<<N_NODES / 8, 256>>>(x, proj_W, proj_b, bn1_g, bn1_b);   // 2
    k_edgehidden<<<N_EDGES / 2, 256>>>(ea, eW1, eb1, bn2_g, bn2_b);  // 3

    // theta split in 3 so ncu (-s 5 -c 1) captures a theta slice at launch 6
    k_theta<<<417, 256, TH_SMEM_TOTAL>>>(eb2, 0);     // 4
    k_theta<<<417, 256, TH_SMEM_TOTAL>>>(eb2, 417);   // 5
    k_theta<<<416, 256, TH_SMEM_TOTAL>>>(eb2, 834);   // 6  <- profiled

    for (int s = 0; s < STEPS; s++) {
        k_msg<<<(N_EDGES * 32) / 256, 256>>>(ei);
        k_update<<<N_NODES / 8, 256>>>(root, cb, W_ih, W_hh, b_ih, b_hh,
                                       out, s == STEPS - 1 ? 1 : 0);
    }
}

// round 5
// speedup vs baseline: 2.0768x; 1.1091x over previous
#include <cuda_runtime.h>
#include <cuda_fp16.h>
#include <cstdint>
#include <math.h>

#define N_NODES 40000
#define N_EDGES 160000
#define DIN 64
#define D 32
#define EIN 16
#define EH 128
#define STEPS 3
#define EPS_BN 1e-5f

// ---------------- device scratch (no allocation allowed) ----------------
__device__ float g_h[N_NODES * D];                  // node features / GRU hidden
__device__ float g_eh[N_EDGES * EH];                // edge hidden (82 MB)
__device__ uint32_t g_theta[(size_t)N_EDGES * 512]; // per-edge mats, fp16 pairs (327 MB)
__device__ float g_agg[N_NODES * D];                // scatter-add accumulator
__device__ __half g_Bh[1024 * 128];                 // fp16 W2^T, [n][k-permuted] (256 KB)

// k-permutation so one LDS.64 yields both mma B (or A) fragment registers:
// slot(k) = (k/16)*16 + ((k%8)/2)*4 + (k%2) + ((k%16)/8)*2
__device__ __host__ __forceinline__ int kslot(int k) {
    return ((k >> 4) << 4) + (((k & 7) >> 1) << 2) + (k & 1) + (((k >> 3) & 1) << 1);
}

// ---------------- fp16 MMA helper (sm_103-safe, no 'a' features) -----------
__device__ __forceinline__ void mma_f16_16x8x16(float c[4], const uint32_t a[4],
                                                uint32_t b0, uint32_t b1) {
    asm volatile(
        "mma.sync.aligned.m16n8k16.row.col.f32.f16.f16.f32 "
        "{%0,%1,%2,%3}, {%4,%5,%6,%7}, {%8,%9}, {%0,%1,%2,%3};"
        : "+f"(c[0]), "+f"(c[1]), "+f"(c[2]), "+f"(c[3])
        : "r"(a[0]), "r"(a[1]), "r"(a[2]), "r"(a[3]), "r"(b0), "r"(b1));
}

__device__ __forceinline__ uint32_t smem_u32(const void* p) {
    uint32_t a;
    asm("{ .reg .u64 t; cvta.to.shared.u64 t, %1; cvt.u32.u64 %0, t; }" : "=r"(a) : "l"(p));
    return a;
}
#define CP_ASYNC16(dst_u32, src_ptr) \
    asm volatile("cp.async.cg.shared.global [%0], [%1], 16;" :: "r"(dst_u32), "l"(src_ptr))
#define CP_COMMIT() asm volatile("cp.async.commit_group;")
#define CP_WAIT0() asm volatile("cp.async.wait_group 0;")

// ---------------- K0: fp16 B = W2^T image, [n][slot(k)] ---------------------
__global__ void __launch_bounds__(256) k_prepB(const float* __restrict__ eW2) {
    int i = blockIdx.x * 256 + threadIdx.x; // 131072 total
    int k = i >> 10;       // 0..127 (eW2 row)
    int n = i & 1023;      // 0..1023 (coalesced read)
    g_Bh[n * 128 + kslot(k)] = __float2half_rn(eW2[k * 1024 + n]);
}

// ---------------- K1: h = relu(bn(x @ proj_W + proj_b)); also zero g_agg ----
__global__ void __launch_bounds__(256) k_proj(const float* __restrict__ x,
                                              const float* __restrict__ W,
                                              const float* __restrict__ b,
                                              const float* __restrict__ g,
                                              const float* __restrict__ bb) {
    __shared__ float Ws[DIN * D];
    int tid = threadIdx.x;
    for (int i = tid; i < DIN * D; i += 256) Ws[i] = W[i];
    __syncthreads();
    int lane = tid & 31;
    int node = blockIdx.x * 8 + (tid >> 5);
    if (node >= N_NODES) return;
    float x0 = x[node * DIN + lane];
    float x1 = x[node * DIN + 32 + lane];
    float acc = 0.f;
#pragma unroll
    for (int i = 0; i < 32; i++) {
        acc = fmaf(__shfl_sync(0xffffffffu, x0, i), Ws[i * D + lane], acc);
        acc = fmaf(__shfl_sync(0xffffffffu, x1, i), Ws[(32 + i) * D + lane], acc);
    }
    float s = g[lane] * rsqrtf(1.f + EPS_BN);
    float v = (acc + b[lane]) * s + bb[lane];
    g_h[node * D + lane] = fmaxf(v, 0.f);
    g_agg[node * D + lane] = 0.f;
}

// ---------------- K2: eh = relu(bn(edge_attr @ eW1 + eb1)), 32 edges/block --
__global__ void __launch_bounds__(256) k_edgehidden(const float* __restrict__ ea,
                                                    const float* __restrict__ W1,
                                                    const float* __restrict__ b1,
                                                    const float* __restrict__ g,
                                                    const float* __restrict__ bb) {
    __shared__ float4 eas[32][4];
    int tid = threadIdx.x;
    int e0 = blockIdx.x * 32;
    if (tid < 128)
        eas[tid >> 2][tid & 3] = reinterpret_cast<const float4*>(ea)[e0 * 4 + tid];
    int k = tid & 127;
    int half = tid >> 7;
    float w[16];
#pragma unroll
    for (int i = 0; i < 16; i++) w[i] = W1[i * EH + k];
    float s = g[k] * rsqrtf(1.f + EPS_BN);
    float bias = b1[k], beta = bb[k];
    __syncthreads();
#pragma unroll
    for (int i = 0; i < 16; i++) {
        int e = half * 16 + i;
        float4 a0 = eas[e][0], a1 = eas[e][1], a2 = eas[e][2], a3 = eas[e][3];
        float acc = w[0] * a0.x;
        acc = fmaf(w[1], a0.y, acc);  acc = fmaf(w[2], a0.z, acc);
        acc = fmaf(w[3], a0.w, acc);  acc = fmaf(w[4], a1.x, acc);
        acc = fmaf(w[5], a1.y, acc);  acc = fmaf(w[6], a1.z, acc);
        acc = fmaf(w[7], a1.w, acc);  acc = fmaf(w[8], a2.x, acc);
        acc = fmaf(w[9], a2.y, acc);  acc = fmaf(w[10], a2.z, acc);
        acc = fmaf(w[11], a2.w, acc); acc = fmaf(w[12], a3.x, acc);
        acc = fmaf(w[13], a3.y, acc); acc = fmaf(w[14], a3.z, acc);
        acc = fmaf(w[15], a3.w, acc);
        float v = (acc + bias) * s + beta;
        g_eh[(size_t)(e0 + e) * EH + k] = fmaxf(v, 0.f);
    }
}

// ---------------- K3: theta = eh @ eW2 + eb2 (fp16 m16n8k16, cp.async) ------
// Block: M=128 x full N=1024 (8 panels of 128). K=128 resident, k-permuted.
#define A_LDH 136
#define B_LDH 136
#define TH_AS 0
#define TH_B0 (128 * A_LDH * 2)                 // 34816
#define TH_B1 (TH_B0 + 128 * B_LDH * 2)         // 69632
#define TH_BIAS (TH_B1 + 128 * B_LDH * 2)       // 104448
#define TH_SMEM_TOTAL (TH_BIAS + 4096)          // 108544

__global__ void __launch_bounds__(256, 2) k_theta(const float* __restrict__ eb2) {
    extern __shared__ char smem[];
    __half* As = reinterpret_cast<__half*>(smem + TH_AS);
    float* biass = reinterpret_cast<float*>(smem + TH_BIAS);
    const int tid = threadIdx.x, warp = tid >> 5, lane = tid & 31;
    const int m0 = blockIdx.x * 128;
    const uint32_t sb = smem_u32(smem);

    for (int i = tid; i < 1024; i += 256) biass[i] = eb2[i];

    // A tile: 128x128 fp32 -> fp16, k-permuted rows
#pragma unroll
    for (int it = 0; it < 16; it++) {
        int idx = it * 256 + tid;
        int row = idx >> 5;
        int c4 = (idx & 31) << 2;
        float4 v = *reinterpret_cast<const float4*>(&g_eh[(size_t)(m0 + row) * EH + c4]);
        __half2 p0 = __floats2half2_rn(v.x, v.y);
        __half2 p1 = __floats2half2_rn(v.z, v.w);
        int sbase = ((c4 >> 4) << 4) + (((c4 >> 3) & 1) << 1) + (((c4 & 7) >> 1) << 2);
        *reinterpret_cast<uint32_t*>(&As[row * A_LDH + sbase]) =
            *reinterpret_cast<uint32_t*>(&p0);
        *reinterpret_cast<uint32_t*>(&As[row * A_LDH + sbase + 4]) =
            *reinterpret_cast<uint32_t*>(&p1);
    }

    // B panel 0 via cp.async into buffer 0
    {
        const char* src = reinterpret_cast<const char*>(g_Bh);
#pragma unroll
        for (int it = 0; it < 8; it++) {
            int idx = it * 256 + tid;           // 2048 x 16B
            int row = idx >> 4, q = idx & 15;
            CP_ASYNC16(sb + TH_B0 + row * (B_LDH * 2) + q * 16, src + idx * 16);
        }
        CP_COMMIT();
    }
    CP_WAIT0();
    __syncthreads();

    const int wm = (warp & 3) * 32;
    const int wn = (warp >> 2) * 64;
    const int lq = lane >> 2;
    const int lr = lane & 3;

#pragma unroll 1
    for (int p = 0; p < 8; p++) {
        const __half* Bs = reinterpret_cast<const __half*>(smem + ((p & 1) ? TH_B1 : TH_B0));
        // prefetch next panel into the other buffer (async, overlaps HMMA)
        if (p < 7) {
            uint32_t dstb = sb + ((p & 1) ? TH_B0 : TH_B1);
            const char* src = reinterpret_cast<const char*>(g_Bh) + (size_t)(p + 1) * 32768;
#pragma unroll
            for (int it = 0; it < 8; it++) {
                int idx = it * 256 + tid;
                int row = idx >> 4, q = idx & 15;
                CP_ASYNC16(dstb + row * (B_LDH * 2) + q * 16, src + idx * 16);
            }
            CP_COMMIT();
        }

        float c[2][8][4];
#pragma unroll
        for (int mt = 0; mt < 2; mt++)
#pragma unroll
            for (int nt = 0; nt < 8; nt++)
#pragma unroll
                for (int i = 0; i < 4; i++) c[mt][nt][i] = 0.f;

#pragma unroll
        for (int ks = 0; ks < 8; ks++) {
            int koff = ks * 16 + lr * 4;
            uint32_t a[2][4];
#pragma unroll
            for (int mt = 0; mt < 2; mt++) {
                int r = wm + mt * 16 + lq;
                uint2 ua = *reinterpret_cast<const uint2*>(&As[r * A_LDH + koff]);
                uint2 ub = *reinterpret_cast<const uint2*>(&As[(r + 8) * A_LDH + koff]);
                a[mt][0] = ua.x; a[mt][2] = ua.y;
                a[mt][1] = ub.x; a[mt][3] = ub.y;
            }
#pragma unroll
            for (int nt = 0; nt < 8; nt++) {
                int n = wn + nt * 8 + lq;
                uint2 vb = *reinterpret_cast<const uint2*>(&Bs[n * B_LDH + koff]);
                mma_f16_16x8x16(c[0][nt], a[0], vb.x, vb.y);
                mma_f16_16x8x16(c[1][nt], a[1], vb.x, vb.y);
            }
        }

        // epilogue: + bias, pack fp16 pairs, store (gmem only; no smem hazard)
#pragma unroll
        for (int mt = 0; mt < 2; mt++) {
#pragma unroll
            for (int nt = 0; nt < 8; nt++) {
                int row = m0 + wm + mt * 16 + lq;
                int col = p * 128 + wn + nt * 8 + lr * 2;
                float bv0 = biass[col], bv1 = biass[col + 1];
                __half2 p0 = __floats2half2_rn(c[mt][nt][0] + bv0, c[mt][nt][1] + bv1);
                __half2 p1 = __floats2half2_rn(c[mt][nt][2] + bv0, c[mt][nt][3] + bv1);
                g_theta[((size_t)row * 1024 + col) >> 1] = *reinterpret_cast<uint32_t*>(&p0);
                g_theta[((size_t)(row + 8) * 1024 + col) >> 1] = *reinterpret_cast<uint32_t*>(&p1);
            }
        }

        if (p < 7) CP_WAIT0();
        __syncthreads();
    }
}

// ---------------- K5: msg = h[src] @ theta_e ; atomic scatter to agg[dst] ----
__global__ void __launch_bounds__(256) k_msg(const int* __restrict__ ei) {
    int gw = (blockIdx.x * blockDim.x + threadIdx.x) >> 5;
    if (gw >= N_EDGES) return;
    int lane = threadIdx.x & 31;
    int src = __ldg(&ei[gw]);
    int dst = __ldg(&ei[N_EDGES + gw]);
    float hv = g_h[src * D + lane];
    const uint2* th = reinterpret_cast<const uint2*>(g_theta + (size_t)gw * 512);
    const int q = lane >> 3;
    const int c8 = lane & 7;
    float a0 = 0.f, a1 = 0.f, a2 = 0.f, a3 = 0.f;
#pragma unroll
    for (int it = 0; it < 8; it++) {
        int r = it * 4 + q;
        uint2 u = __ldcs(&th[r * 8 + c8]);  // streaming: evict-first
        float hr = __shfl_sync(0xffffffffu, hv, r);
        float2 f01 = __half22float2(*reinterpret_cast<const __half2*>(&u.x));
        float2 f23 = __half22float2(*reinterpret_cast<const __half2*>(&u.y));
        a0 = fmaf(hr, f01.x, a0);
        a1 = fmaf(hr, f01.y, a1);
        a2 = fmaf(hr, f23.x, a2);
        a3 = fmaf(hr, f23.y, a3);
    }
    a0 += __shfl_xor_sync(0xffffffffu, a0, 8);
    a1 += __shfl_xor_sync(0xffffffffu, a1, 8);
    a2 += __shfl_xor_sync(0xffffffffu, a2, 8);
    a3 += __shfl_xor_sync(0xffffffffu, a3, 8);
    a0 += __shfl_xor_sync(0xffffffffu, a0, 16);
    a1 += __shfl_xor_sync(0xffffffffu, a1, 16);
    a2 += __shfl_xor_sync(0xffffffffu, a2, 16);
    a3 += __shfl_xor_sync(0xffffffffu, a3, 16);
    if (lane < 8) {
        float* dp = &g_agg[dst * D + c8 * 4];
        atomicAdd(dp + 0, a0);
        atomicAdd(dp + 1, a1);
        atomicAdd(dp + 2, a2);
        atomicAdd(dp + 3, a3);
    }
}

// ---------------- K6: conv + relu + GRU cell, in-place; resets agg ----------
__global__ void __launch_bounds__(256) k_update(const float* __restrict__ root,
                                                const float* __restrict__ cb,
                                                const float* __restrict__ W_ih,
                                                const float* __restrict__ W_hh,
                                                const float* __restrict__ b_ih,
                                                const float* __restrict__ b_hh,
                                                float* __restrict__ out,
                                                int write_out) {
    __shared__ float s_wih[D * 96];
    __shared__ float s_whh[D * 96];
    __shared__ float s_root[D * D];
    __shared__ float s_bih[96], s_bhh[96], s_cb[D];
    int tid = threadIdx.x;
    for (int idx = tid; idx < 96 * D; idx += 256) {
        int j = idx / D, i = idx % D;
        s_wih[i * 96 + j] = W_ih[idx];
        s_whh[i * 96 + j] = W_hh[idx];
    }
    for (int idx = tid; idx < D * D; idx += 256) s_root[idx] = root[idx];
    if (tid < 96) { s_bih[tid] = b_ih[tid]; s_bhh[tid] = b_hh[tid]; }
    if (tid < D) s_cb[tid] = cb[tid];
    __syncthreads();

    int lane = tid & 31;
    int v = blockIdx.x * 8 + (tid >> 5);
    if (v >= N_NODES) return;

    float hv = g_h[v * D + lane];
    float conv = g_agg[v * D + lane] + s_cb[lane];
    g_agg[v * D + lane] = 0.f;
#pragma unroll
    for (int i = 0; i < 32; i++)
        conv = fmaf(__shfl_sync(0xffffffffu, hv, i), s_root[i * D + lane], conv);
    float m = fmaxf(conv, 0.f);

    float gr = s_bih[lane], gz = s_bih[32 + lane], gn = s_bih[64 + lane];
    float hr = s_bhh[lane], hz = s_bhh[32 + lane], hn = s_bhh[64 + lane];
#pragma unroll
    for (int i = 0; i < 32; i++) {
        float mi = __shfl_sync(0xffffffffu, m, i);
        float hi = __shfl_sync(0xffffffffu, hv, i);
        const float* wi = &s_wih[i * 96];
        const float* wh = &s_whh[i * 96];
        gr = fmaf(mi, wi[lane], gr);
        gz = fmaf(mi, wi[32 + lane], gz);
        gn = fmaf(mi, wi[64 + lane], gn);
        hr = fmaf(hi, wh[lane], hr);
        hz = fmaf(hi, wh[32 + lane], hz);
        hn = fmaf(hi, wh[64 + lane], hn);
    }
    float r = 1.f / (1.f + expf(-(gr + hr)));
    float z = 1.f / (1.f + expf(-(gz + hz)));
    float n = tanhf(gn + r * hn);
    float hnew = (1.f - z) * n + z * hv;
    g_h[v * D + lane] = hnew;
    if (write_out) out[v * D + lane] = hnew;
}

// ---------------- launch ----------------
extern "C" void kernel_launch(void* const* d_in, const int* in_sizes, int n_in,
                              void* d_out, int out_size) {
    (void)in_sizes; (void)n_in; (void)out_size;
    const float* x        = (const float*)d_in[0];
    const int*   ei       = (const int*)d_in[1];
    const float* ea       = (const float*)d_in[2];
    const float* proj_W   = (const float*)d_in[3];
    const float* proj_b   = (const float*)d_in[4];
    const float* bn1_g    = (const float*)d_in[5];
    const float* bn1_b    = (const float*)d_in[6];
    const float* eW1      = (const float*)d_in[7];
    const float* eb1      = (const float*)d_in[8];
    const float* bn2_g    = (const float*)d_in[9];
    const float* bn2_b    = (const float*)d_in[10];
    const float* eW2      = (const float*)d_in[11];
    const float* eb2      = (const float*)d_in[12];
    const float* root     = (const float*)d_in[13];
    const float* cb       = (const float*)d_in[14];
    const float* W_ih     = (const float*)d_in[15];
    const float* W_hh     = (const float*)d_in[16];
    const float* b_ih     = (const float*)d_in[17];
    const float* b_hh     = (const float*)d_in[18];
    float* out = (float*)d_out;

    static int attr_set = 0;
    if (!attr_set) {
        cudaFuncSetAttribute(k_theta, cudaFuncAttributeMaxDynamicSharedMemorySize,
                             TH_SMEM_TOTAL);
        attr_set = 1;
    }

    k_prepB<<<512, 256>>>(eW2);                                      // 1
    k_proj<<<N_NODES / 8, 256>>>(x, proj_W, proj_b, bn1_g, bn1_b);   // 2
    k_edgehidden<<<N_EDGES / 32, 256>>>(ea, eW1, eb1, bn2_g, bn2_b); // 3
    k_theta<<<N_EDGES / 128, 256, TH_SMEM_TOTAL>>>(eb2);             // 4

    for (int s = 0; s < STEPS; s++) {
        k_msg<<<(N_EDGES * 32) / 256, 256>>>(ei);                    // 5,7,9
        k_update<<<N_NODES / 8, 256>>>(root, cb, W_ih, W_hh, b_ih, b_hh,
                                       out, s == STEPS - 1 ? 1 : 0); // 6<-prof,8,10
    }
}

// round 6
// speedup vs baseline: 3.7051x; 1.7840x over previous
#include <cuda_runtime.h>
#include <cuda_fp16.h>
#include <cstdint>
#include <math.h>

#define N_NODES 40000
#define N_EDGES 160000
#define DIN 64
#define D 32
#define EIN 16
#define EH 128
#define STEPS 3
#define EPS_BN 1e-5f

// ---------------- device scratch (no allocation allowed) ----------------
__device__ float g_h[N_NODES * D];                  // node features / GRU hidden
__device__ float g_eh[N_EDGES * EH];                // edge hidden (82 MB)
__device__ uint32_t g_theta[(size_t)N_EDGES * 512]; // per-edge mats, fp16 pairs (327 MB)
__device__ float g_agg[N_NODES * D];                // scatter-add accumulator
__device__ __half g_Bh[1024 * 128];                 // fp16 W2^T, [n][k-permuted] (256 KB)
__device__ __half g_Wcat[128 * 32];                 // [W_hh(96) | root^T(32)] fp16
__device__ __half g_Wih[96 * 32];                   // W_ih fp16

// k-permutation: one LDS.64 yields both mma fragment registers
__device__ __host__ __forceinline__ int kslot(int k) {
    return ((k >> 4) << 4) + (((k & 7) >> 1) << 2) + (k & 1) + (((k >> 3) & 1) << 1);
}

__device__ __forceinline__ void mma_f16_16x8x16(float c[4], const uint32_t a[4],
                                                uint32_t b0, uint32_t b1) {
    asm volatile(
        "mma.sync.aligned.m16n8k16.row.col.f32.f16.f16.f32 "
        "{%0,%1,%2,%3}, {%4,%5,%6,%7}, {%8,%9}, {%0,%1,%2,%3};"
        : "+f"(c[0]), "+f"(c[1]), "+f"(c[2]), "+f"(c[3])
        : "r"(a[0]), "r"(a[1]), "r"(a[2]), "r"(a[3]), "r"(b0), "r"(b1));
}

__device__ __forceinline__ uint32_t smem_u32(const void* p) {
    uint32_t a;
    asm("{ .reg .u64 t; cvta.to.shared.u64 t, %1; cvt.u32.u64 %0, t; }" : "=r"(a) : "l"(p));
    return a;
}
#define CP_ASYNC16(dst_u32, src_ptr) \
    asm volatile("cp.async.cg.shared.global [%0], [%1], 16;" :: "r"(dst_u32), "l"(src_ptr))
#define CP_COMMIT() asm volatile("cp.async.commit_group;")
#define CP_WAIT0() asm volatile("cp.async.wait_group 0;")
#define CP_WAIT1() asm volatile("cp.async.wait_group 1;")

// ---------------- K0a: fp16 B = W2^T image, [n][slot(k)] --------------------
__global__ void __launch_bounds__(256) k_prepB(const float* __restrict__ eW2) {
    int i = blockIdx.x * 256 + threadIdx.x; // 131072 total
    int k = i >> 10;
    int n = i & 1023;
    g_Bh[n * 128 + kslot(k)] = __float2half_rn(eW2[k * 1024 + n]);
}

// ---------------- K0b: fp16 GRU weights --------------------------------------
__global__ void __launch_bounds__(256) k_prepW(const float* __restrict__ W_hh,
                                               const float* __restrict__ root,
                                               const float* __restrict__ W_ih) {
    int tid = threadIdx.x;
    for (int i = tid; i < 128 * 32; i += 256) {
        int n = i >> 5, k = i & 31;
        float v = (n < 96) ? W_hh[n * 32 + k] : root[k * 32 + (n - 96)];
        g_Wcat[i] = __float2half_rn(v);
    }
    for (int i = tid; i < 96 * 32; i += 256)
        g_Wih[i] = __float2half_rn(W_ih[i]);
}

// ---------------- K1: h = relu(bn(x @ proj_W + proj_b)); zero g_agg ---------
__global__ void __launch_bounds__(256) k_proj(const float* __restrict__ x,
                                              const float* __restrict__ W,
                                              const float* __restrict__ b,
                                              const float* __restrict__ g,
                                              const float* __restrict__ bb) {
    __shared__ float Ws[DIN * D];
    int tid = threadIdx.x;
    for (int i = tid; i < DIN * D; i += 256) Ws[i] = W[i];
    __syncthreads();
    int lane = tid & 31;
    int node = blockIdx.x * 8 + (tid >> 5);
    if (node >= N_NODES) return;
    float x0 = x[node * DIN + lane];
    float x1 = x[node * DIN + 32 + lane];
    float acc = 0.f;
#pragma unroll
    for (int i = 0; i < 32; i++) {
        acc = fmaf(__shfl_sync(0xffffffffu, x0, i), Ws[i * D + lane], acc);
        acc = fmaf(__shfl_sync(0xffffffffu, x1, i), Ws[(32 + i) * D + lane], acc);
    }
    float s = g[lane] * rsqrtf(1.f + EPS_BN);
    float v = (acc + b[lane]) * s + bb[lane];
    g_h[node * D + lane] = fmaxf(v, 0.f);
    g_agg[node * D + lane] = 0.f;
}

// ---------------- K2: eh = relu(bn(edge_attr @ eW1 + eb1)) ------------------
__global__ void __launch_bounds__(256) k_edgehidden(const float* __restrict__ ea,
                                                    const float* __restrict__ W1,
                                                    const float* __restrict__ b1,
                                                    const float* __restrict__ g,
                                                    const float* __restrict__ bb) {
    __shared__ float4 eas[32][4];
    int tid = threadIdx.x;
    int e0 = blockIdx.x * 32;
    if (tid < 128)
        eas[tid >> 2][tid & 3] = reinterpret_cast<const float4*>(ea)[e0 * 4 + tid];
    int k = tid & 127;
    int half_ = tid >> 7;
    float w[16];
#pragma unroll
    for (int i = 0; i < 16; i++) w[i] = W1[i * EH + k];
    float s = g[k] * rsqrtf(1.f + EPS_BN);
    float bias = b1[k], beta = bb[k];
    __syncthreads();
#pragma unroll
    for (int i = 0; i < 16; i++) {
        int e = half_ * 16 + i;
        float4 a0 = eas[e][0], a1 = eas[e][1], a2 = eas[e][2], a3 = eas[e][3];
        float acc = w[0] * a0.x;
        acc = fmaf(w[1], a0.y, acc);  acc = fmaf(w[2], a0.z, acc);
        acc = fmaf(w[3], a0.w, acc);  acc = fmaf(w[4], a1.x, acc);
        acc = fmaf(w[5], a1.y, acc);  acc = fmaf(w[6], a1.z, acc);
        acc = fmaf(w[7], a1.w, acc);  acc = fmaf(w[8], a2.x, acc);
        acc = fmaf(w[9], a2.y, acc);  acc = fmaf(w[10], a2.z, acc);
        acc = fmaf(w[11], a2.w, acc); acc = fmaf(w[12], a3.x, acc);
        acc = fmaf(w[13], a3.y, acc); acc = fmaf(w[14], a3.z, acc);
        acc = fmaf(w[15], a3.w, acc);
        float v = (acc + bias) * s + beta;
        g_eh[(size_t)(e0 + e) * EH + k] = fmaxf(v, 0.f);
    }
}

// ---------------- K3: theta GEMM v3: A-hoisted regs + staged stores ---------
#define A_LDH 136
#define B_LDH 136
#define TH_AS 0                                 // A staging, then output staging
#define TH_B0 (128 * A_LDH * 2)                 // 34816
#define TH_B1 (TH_B0 + 128 * B_LDH * 2)         // 69632
#define TH_BIAS (TH_B1 + 128 * B_LDH * 2)       // 104448
#define TH_SMEM_TOTAL (TH_BIAS + 4096)          // 108544

__global__ void __launch_bounds__(256) k_theta(const float* __restrict__ eb2) {
    extern __shared__ char smem[];
    __half* As = reinterpret_cast<__half*>(smem + TH_AS);
    uint32_t* Stg = reinterpret_cast<uint32_t*>(smem + TH_AS); // reused after A consumed
    float* biass = reinterpret_cast<float*>(smem + TH_BIAS);
    const int tid = threadIdx.x, warp = tid >> 5, lane = tid & 31;
    const int m0 = blockIdx.x * 128;
    const uint32_t sb = smem_u32(smem);

    for (int i = tid; i < 1024; i += 256) biass[i] = eb2[i];

    // issue cp.async: panel0 -> B0 (group0), panel1 -> B1 (group1)
    {
        const char* src = reinterpret_cast<const char*>(g_Bh);
#pragma unroll
        for (int it = 0; it < 8; it++) {
            int idx = it * 256 + tid;
            int row = idx >> 4, q = idx & 15;
            CP_ASYNC16(sb + TH_B0 + row * (B_LDH * 2) + q * 16, src + idx * 16);
        }
        CP_COMMIT();
#pragma unroll
        for (int it = 0; it < 8; it++) {
            int idx = it * 256 + tid;
            int row = idx >> 4, q = idx & 15;
            CP_ASYNC16(sb + TH_B1 + row * (B_LDH * 2) + q * 16, src + 32768 + idx * 16);
        }
        CP_COMMIT();
    }

    // A tile: 128x128 fp32 -> fp16, k-permuted, into As
#pragma unroll
    for (int it = 0; it < 16; it++) {
        int idx = it * 256 + tid;
        int row = idx >> 5;
        int c4 = (idx & 31) << 2;
        float4 v = *reinterpret_cast<const float4*>(&g_eh[(size_t)(m0 + row) * EH + c4]);
        __half2 p0 = __floats2half2_rn(v.x, v.y);
        __half2 p1 = __floats2half2_rn(v.z, v.w);
        int sbase = ((c4 >> 4) << 4) + (((c4 >> 3) & 1) << 1) + (((c4 & 7) >> 1) << 2);
        *reinterpret_cast<uint32_t*>(&As[row * A_LDH + sbase]) =
            *reinterpret_cast<uint32_t*>(&p0);
        *reinterpret_cast<uint32_t*>(&As[row * A_LDH + sbase + 4]) =
            *reinterpret_cast<uint32_t*>(&p1);
    }
    CP_WAIT1();        // panel0 resident
    __syncthreads();

    const int wm = (warp & 3) * 32;
    const int wn = (warp >> 2) * 64;
    const int lq = lane >> 2;
    const int lr = lane & 3;

    // hoist ALL A fragments into registers (reused across the 8 panels)
    uint32_t aF[8][2][4];
#pragma unroll
    for (int ks = 0; ks < 8; ks++) {
        int koff = ks * 16 + lr * 4;
#pragma unroll
        for (int mt = 0; mt < 2; mt++) {
            int r = wm + mt * 16 + lq;
            uint2 ua = *reinterpret_cast<const uint2*>(&As[r * A_LDH + koff]);
            uint2 ub = *reinterpret_cast<const uint2*>(&As[(r + 8) * A_LDH + koff]);
            aF[ks][mt][0] = ua.x; aF[ks][mt][2] = ua.y;
            aF[ks][mt][1] = ub.x; aF[ks][mt][3] = ub.y;
        }
    }

#pragma unroll 1
    for (int p = 0; p < 8; p++) {
        const __half* Bs = reinterpret_cast<const __half*>(smem + ((p & 1) ? TH_B1 : TH_B0));

        float c[2][8][4];
#pragma unroll
        for (int mt = 0; mt < 2; mt++)
#pragma unroll
            for (int nt = 0; nt < 8; nt++)
#pragma unroll
                for (int i = 0; i < 4; i++) c[mt][nt][i] = 0.f;

#pragma unroll
        for (int ks = 0; ks < 8; ks++) {
            int koff = ks * 16 + lr * 4;
#pragma unroll
            for (int nt = 0; nt < 8; nt++) {
                int n = wn + nt * 8 + lq;
                uint2 vb = *reinterpret_cast<const uint2*>(&Bs[n * B_LDH + koff]);
                mma_f16_16x8x16(c[0][nt], aF[ks][0], vb.x, vb.y);
                mma_f16_16x8x16(c[1][nt], aF[ks][1], vb.x, vb.y);
            }
        }
        __syncthreads(); // MMA(p) done by all; prev copy-out done by all

        // prefetch panel p+2 into the buffer just freed
        if (p < 6) {
            uint32_t dstb = sb + ((p & 1) ? TH_B1 : TH_B0);
            const char* src = reinterpret_cast<const char*>(g_Bh) + (size_t)(p + 2) * 32768;
#pragma unroll
            for (int it = 0; it < 8; it++) {
                int idx = it * 256 + tid;
                int row = idx >> 4, q = idx & 15;
                CP_ASYNC16(dstb + row * (B_LDH * 2) + q * 16, src + idx * 16);
            }
            CP_COMMIT();
        }

        // stage: bias add + fp16 pack -> conflict-free pitch-68 smem
#pragma unroll
        for (int mt = 0; mt < 2; mt++) {
#pragma unroll
            for (int nt = 0; nt < 8; nt++) {
                int rowl = wm + mt * 16 + lq;
                int col = wn + nt * 8 + lr * 2;
                float bv0 = biass[p * 128 + col], bv1 = biass[p * 128 + col + 1];
                __half2 h0 = __floats2half2_rn(c[mt][nt][0] + bv0, c[mt][nt][1] + bv1);
                __half2 h1 = __floats2half2_rn(c[mt][nt][2] + bv0, c[mt][nt][3] + bv1);
                Stg[rowl * 68 + (col >> 1)] = *reinterpret_cast<uint32_t*>(&h0);
                Stg[(rowl + 8) * 68 + (col >> 1)] = *reinterpret_cast<uint32_t*>(&h1);
            }
        }

        if (p < 6) CP_WAIT1();          // panel p+1 ready (p+2 still in flight)
        else if (p == 6) CP_WAIT0();    // panel 7 ready
        __syncthreads();

        // coalesced copy-out: 128 rows x 256B
#pragma unroll
        for (int it = 0; it < 8; it++) {
            int idx = it * 256 + tid;
            int row = idx >> 4, q = idx & 15;
            uint4 u = *reinterpret_cast<const uint4*>(&Stg[row * 68 + q * 4]);
            reinterpret_cast<uint4*>(g_theta)[(size_t)(m0 + row) * 128 + p * 16 + q] = u;
        }
    }
}

// ---------------- K5: msg = h[src] @ theta_e ; atomic scatter ---------------
__global__ void __launch_bounds__(256) k_msg(const int* __restrict__ ei) {
    int gw = (blockIdx.x * blockDim.x + threadIdx.x) >> 5;
    if (gw >= N_EDGES) return;
    int lane = threadIdx.x & 31;
    int src = __ldg(&ei[gw]);
    int dst = __ldg(&ei[N_EDGES + gw]);
    float hv = g_h[src * D + lane];
    const uint2* th = reinterpret_cast<const uint2*>(g_theta + (size_t)gw * 512);
    const int q = lane >> 3;
    const int c8 = lane & 7;
    float a0 = 0.f, a1 = 0.f, a2 = 0.f, a3 = 0.f;
#pragma unroll
    for (int it = 0; it < 8; it++) {
        int r = it * 4 + q;
        uint2 u = __ldcs(&th[r * 8 + c8]);
        float hr = __shfl_sync(0xffffffffu, hv, r);
        float2 f01 = __half22float2(*reinterpret_cast<const __half2*>(&u.x));
        float2 f23 = __half22float2(*reinterpret_cast<const __half2*>(&u.y));
        a0 = fmaf(hr, f01.x, a0);
        a1 = fmaf(hr, f01.y, a1);
        a2 = fmaf(hr, f23.x, a2);
        a3 = fmaf(hr, f23.y, a3);
    }
    a0 += __shfl_xor_sync(0xffffffffu, a0, 8);
    a1 += __shfl_xor_sync(0xffffffffu, a1, 8);
    a2 += __shfl_xor_sync(0xffffffffu, a2, 8);
    a3 += __shfl_xor_sync(0xffffffffu, a3, 8);
    a0 += __shfl_xor_sync(0xffffffffu, a0, 16);
    a1 += __shfl_xor_sync(0xffffffffu, a1, 16);
    a2 += __shfl_xor_sync(0xffffffffu, a2, 16);
    a3 += __shfl_xor_sync(0xffffffffu, a3, 16);
    if (lane < 8) {
        float* dp = &g_agg[dst * D + c8 * 4];
        atomicAdd(dp + 0, a0);
        atomicAdd(dp + 1, a1);
        atomicAdd(dp + 2, a2);
        atomicAdd(dp + 3, a3);
    }
}

// ---------------- K6 v2: conv + relu + GRU via HMMA, 128 nodes/block --------
// smem layout (dynamic):
#define UP_H16 0                         // half [128][36]
#define UP_M16 (UP_H16 + 9216)           // half [128][36]
#define UP_W1  (UP_M16 + 9216)           // half [128][36]  (W_hh | root^T)
#define UP_W2  (UP_W1 + 9216)            // half [96][36]   (W_ih)
#define UP_HF  (UP_W2 + 6912)            // float [128][36]
#define UP_BIH (UP_HF + 18432)           // float [96]
#define UP_BHH (UP_BIH + 384)            // float [96]
#define UP_CB  (UP_BHH + 384)            // float [32]
#define UP_SMEM_TOTAL (UP_CB + 128)      // 53888

__global__ void __launch_bounds__(256) k_update(const float* __restrict__ cb,
                                                const float* __restrict__ b_ih,
                                                const float* __restrict__ b_hh,
                                                float* __restrict__ out,
                                                int write_out) {
    extern __shared__ char smem[];
    __half* h16 = reinterpret_cast<__half*>(smem + UP_H16);
    __half* m16 = reinterpret_cast<__half*>(smem + UP_M16);
    __half* w1 = reinterpret_cast<__half*>(smem + UP_W1);
    __half* w2 = reinterpret_cast<__half*>(smem + UP_W2);
    float* hf = reinterpret_cast<float*>(smem + UP_HF);
    float* sbih = reinterpret_cast<float*>(smem + UP_BIH);
    float* sbhh = reinterpret_cast<float*>(smem + UP_BHH);
    float* scb = reinterpret_cast<float*>(smem + UP_CB);
    const int tid = threadIdx.x, warp = tid >> 5, lane = tid & 31;
    const int lq = lane >> 2, lr = lane & 3;
    const int node0 = blockIdx.x * 128;
    const int wm = warp * 16;

    // weights + biases to smem
    for (int i = tid; i < 128 * 32; i += 256) {
        int n = i >> 5, k = i & 31;
        w1[n * 36 + k] = g_Wcat[i];
    }
    for (int i = tid; i < 96 * 32; i += 256) {
        int n = i >> 5, k = i & 31;
        w2[n * 36 + k] = g_Wih[i];
    }
    if (tid < 96) { sbih[tid] = b_ih[tid]; sbhh[tid] = b_hh[tid]; }
    if (tid < 32) scb[tid] = cb[tid];

    // h tile: 128 x 32 fp32 -> smem fp32 + fp16 (pad rows -> 0)
#pragma unroll
    for (int it = 0; it < 4; it++) {
        int idx = it * 256 + tid;          // 1024 float4
        int row = idx >> 3;
        int c4 = (idx & 7) << 2;
        int node = node0 + row;
        float4 v = make_float4(0.f, 0.f, 0.f, 0.f);
        if (node < N_NODES)
            v = *reinterpret_cast<const float4*>(&g_h[node * D + c4]);
        *reinterpret_cast<float4*>(&hf[row * 36 + c4]) = v;
        __half2 p0 = __floats2half2_rn(v.x, v.y);
        __half2 p1 = __floats2half2_rn(v.z, v.w);
        uint2 u = make_uint2(*reinterpret_cast<uint32_t*>(&p0),
                             *reinterpret_cast<uint32_t*>(&p1));
        *reinterpret_cast<uint2*>(&h16[row * 36 + c4]) = u;
    }
    __syncthreads();

    // phase 1: [gh | h@root] = h16 @ w1^T   (M=16/warp, N=128, K=32)
    float c1[16][4];
#pragma unroll
    for (int nt = 0; nt < 16; nt++)
#pragma unroll
        for (int i = 0; i < 4; i++) c1[nt][i] = 0.f;
#pragma unroll
    for (int ks = 0; ks < 2; ks++) {
        int kb = ks * 16 + lr * 2;
        uint32_t a[4];
        a[0] = *reinterpret_cast<const uint32_t*>(&h16[(wm + lq) * 36 + kb]);
        a[2] = *reinterpret_cast<const uint32_t*>(&h16[(wm + lq) * 36 + kb + 8]);
        a[1] = *reinterpret_cast<const uint32_t*>(&h16[(wm + lq + 8) * 36 + kb]);
        a[3] = *reinterpret_cast<const uint32_t*>(&h16[(wm + lq + 8) * 36 + kb + 8]);
#pragma unroll
        for (int nt = 0; nt < 16; nt++) {
            int n = nt * 8 + lq;
            uint32_t b0 = *reinterpret_cast<const uint32_t*>(&w1[n * 36 + kb]);
            uint32_t b1 = *reinterpret_cast<const uint32_t*>(&w1[n * 36 + kb + 8]);
            mma_f16_16x8x16(c1[nt], a, b0, b1);
        }
    }

    // conv = agg + h@root + cb ; m = relu ; stage m to smem fp16
    int rowA = wm + lq, rowB = wm + lq + 8;
    int nodeA = node0 + rowA, nodeB = node0 + rowB;
#pragma unroll
    for (int nt = 0; nt < 4; nt++) {
        int jp = nt * 8 + lr * 2;
        float cb0 = scb[jp], cb1 = scb[jp + 1];
        float2 agA = make_float2(0.f, 0.f), agB = make_float2(0.f, 0.f);
        if (nodeA < N_NODES) agA = *reinterpret_cast<const float2*>(&g_agg[nodeA * D + jp]);
        if (nodeB < N_NODES) agB = *reinterpret_cast<const float2*>(&g_agg[nodeB * D + jp]);
        float m0v = fmaxf(c1[12 + nt][0] + agA.x + cb0, 0.f);
        float m1v = fmaxf(c1[12 + nt][1] + agA.y + cb1, 0.f);
        float m2v = fmaxf(c1[12 + nt][2] + agB.x + cb0, 0.f);
        float m3v = fmaxf(c1[12 + nt][3] + agB.y + cb1, 0.f);
        __half2 hA = __floats2half2_rn(m0v, m1v);
        __half2 hB = __floats2half2_rn(m2v, m3v);
        *reinterpret_cast<uint32_t*>(&m16[rowA * 36 + jp]) =
            *reinterpret_cast<uint32_t*>(&hA);
        *reinterpret_cast<uint32_t*>(&m16[rowB * 36 + jp]) =
            *reinterpret_cast<uint32_t*>(&hB);
    }
    __syncthreads();

    // phase 2: gi = m16 @ w2^T  (N=96)
    float c2[12][4];
#pragma unroll
    for (int nt = 0; nt < 12; nt++)
#pragma unroll
        for (int i = 0; i < 4; i++) c2[nt][i] = 0.f;
#pragma unroll
    for (int ks = 0; ks < 2; ks++) {
        int kb = ks * 16 + lr * 2;
        uint32_t a[4];
        a[0] = *reinterpret_cast<const uint32_t*>(&m16[(wm + lq) * 36 + kb]);
        a[2] = *reinterpret_cast<const uint32_t*>(&m16[(wm + lq) * 36 + kb + 8]);
        a[1] = *reinterpret_cast<const uint32_t*>(&m16[(wm + lq + 8) * 36 + kb]);
        a[3] = *reinterpret_cast<const uint32_t*>(&m16[(wm + lq + 8) * 36 + kb + 8]);
#pragma unroll
        for (int nt = 0; nt < 12; nt++) {
            int n = nt * 8 + lq;
            uint32_t b0 = *reinterpret_cast<const uint32_t*>(&w2[n * 36 + kb]);
            uint32_t b1 = *reinterpret_cast<const uint32_t*>(&w2[n * 36 + kb + 8]);
            mma_f16_16x8x16(c2[nt], a, b0, b1);
        }
    }

    // gates + blend + store
#pragma unroll
    for (int nt = 0; nt < 4; nt++) {
        int jp = nt * 8 + lr * 2;
#pragma unroll
        for (int hrow = 0; hrow < 2; hrow++) {
            int node = hrow ? nodeB : nodeA;
            if (node >= N_NODES) continue;
            int rl = hrow ? rowB : rowA;
            float hn0, hn1;
            {
                int ci = 2 * hrow;
                float gr0 = c2[nt][ci] + sbih[jp] + c1[nt][ci] + sbhh[jp];
                float gr1 = c2[nt][ci + 1] + sbih[jp + 1] + c1[nt][ci + 1] + sbhh[jp + 1];
                float gz0 = c2[4 + nt][ci] + sbih[32 + jp] + c1[4 + nt][ci] + sbhh[32 + jp];
                float gz1 = c2[4 + nt][ci + 1] + sbih[33 + jp] + c1[4 + nt][ci + 1] + sbhh[33 + jp];
                float r0 = 1.f / (1.f + expf(-gr0));
                float r1 = 1.f / (1.f + expf(-gr1));
                float z0 = 1.f / (1.f + expf(-gz0));
                float z1 = 1.f / (1.f + expf(-gz1));
                float gn0 = c2[8 + nt][ci] + sbih[64 + jp];
                float gn1 = c2[8 + nt][ci + 1] + sbih[65 + jp];
                float ghn0 = c1[8 + nt][ci] + sbhh[64 + jp];
                float ghn1 = c1[8 + nt][ci + 1] + sbhh[65 + jp];
                float n0 = tanhf(gn0 + r0 * ghn0);
                float n1 = tanhf(gn1 + r1 * ghn1);
                float hv0 = hf[rl * 36 + jp];
                float hv1 = hf[rl * 36 + jp + 1];
                hn0 = (1.f - z0) * n0 + z0 * hv0;
                hn1 = (1.f - z1) * n1 + z1 * hv1;
            }
            float2 hv2 = make_float2(hn0, hn1);
            *reinterpret_cast<float2*>(&g_h[node * D + jp]) = hv2;
            *reinterpret_cast<float2*>(&g_agg[node * D + jp]) = make_float2(0.f, 0.f);
            if (write_out)
                *reinterpret_cast<float2*>(&out[node * D + jp]) = hv2;
        }
    }
}

// ---------------- launch ----------------
extern "C" void kernel_launch(void* const* d_in, const int* in_sizes, int n_in,
                              void* d_out, int out_size) {
    (void)in_sizes; (void)n_in; (void)out_size;
    const float* x        = (const float*)d_in[0];
    const int*   ei       = (const int*)d_in[1];
    const float* ea       = (const float*)d_in[2];
    const float* proj_W   = (const float*)d_in[3];
    const float* proj_b   = (const float*)d_in[4];
    const float* bn1_g    = (const float*)d_in[5];
    const float* bn1_b    = (const float*)d_in[6];
    const float* eW1      = (const float*)d_in[7];
    const float* eb1      = (const float*)d_in[8];
    const float* bn2_g    = (const float*)d_in[9];
    const float* bn2_b    = (const float*)d_in[10];
    const float* eW2      = (const float*)d_in[11];
    const float* eb2      = (const float*)d_in[12];
    const float* root     = (const float*)d_in[13];
    const float* cb       = (const float*)d_in[14];
    const float* W_ih     = (const float*)d_in[15];
    const float* W_hh     = (const float*)d_in[16];
    const float* b_ih     = (const float*)d_in[17];
    const float* b_hh     = (const float*)d_in[18];
    float* out = (float*)d_out;

    static int attr_set = 0;
    if (!attr_set) {
        cudaFuncSetAttribute(k_theta, cudaFuncAttributeMaxDynamicSharedMemorySize,
                             TH_SMEM_TOTAL);
        cudaFuncSetAttribute(k_update, cudaFuncAttributeMaxDynamicSharedMemorySize,
                             UP_SMEM_TOTAL);
        attr_set = 1;
    }

    k_prepB<<<512, 256>>>(eW2);
    k_prepW<<<1, 256>>>(W_hh, root, W_ih);
    k_proj<<<N_NODES / 8, 256>>>(x, proj_W, proj_b, bn1_g, bn1_b);
    k_edgehidden<<<N_EDGES / 32, 256>>>(ea, eW1, eb1, bn2_g, bn2_b);
    k_theta<<<N_EDGES / 128, 256, TH_SMEM_TOTAL>>>(eb2);

    for (int s = 0; s < STEPS; s++) {
        k_msg<<<(N_EDGES * 32) / 256, 256>>>(ei);
        k_update<<<(N_NODES + 127) / 128, 256, UP_SMEM_TOTAL>>>(
            cb, b_ih, b_hh, out, s == STEPS - 1 ? 1 : 0);
    }
}

// round 7
// speedup vs baseline: 3.8826x; 1.0479x over previous
#include <cuda_runtime.h>
#include <cuda_fp16.h>
#include <cstdint>
#include <math.h>

#define N_NODES 40000
#define N_EDGES 160000
#define DIN 64
#define D 32
#define EIN 16
#define EH 128
#define STEPS 3
#define EPS_BN 1e-5f

// ---------------- device scratch (no allocation allowed) ----------------
__device__ float g_h[N_NODES * D];                  // node features / GRU hidden
__device__ uint32_t g_theta[(size_t)N_EDGES * 512]; // per-edge mats, fp16 pairs (327 MB)
__device__ float g_agg[N_NODES * D];                // scatter-add accumulator
__device__ __half g_Bh[1024 * 128];                 // fp16 W2^T, [n][k-permuted] (256 KB)
__device__ __half g_Wcat[128 * 32];                 // [W_hh(96) | root^T(32)] fp16
__device__ __half g_Wih[96 * 32];                   // W_ih fp16
__device__ __half g_W1h[128 * 16];                  // fp16 W1' = W1 * bn-scale, [n][k]
__device__ float g_b1f[128];                        // folded edge-hidden bias

// k-permutation: one LDS.64 yields both mma fragment registers
__device__ __host__ __forceinline__ int kslot(int k) {
    return ((k >> 4) << 4) + (((k & 7) >> 1) << 2) + (k & 1) + (((k >> 3) & 1) << 1);
}

__device__ __forceinline__ void mma_f16_16x8x16(float c[4], const uint32_t a[4],
                                                uint32_t b0, uint32_t b1) {
    asm volatile(
        "mma.sync.aligned.m16n8k16.row.col.f32.f16.f16.f32 "
        "{%0,%1,%2,%3}, {%4,%5,%6,%7}, {%8,%9}, {%0,%1,%2,%3};"
        : "+f"(c[0]), "+f"(c[1]), "+f"(c[2]), "+f"(c[3])
        : "r"(a[0]), "r"(a[1]), "r"(a[2]), "r"(a[3]), "r"(b0), "r"(b1));
}

__device__ __forceinline__ uint32_t smem_u32(const void* p) {
    uint32_t a;
    asm("{ .reg .u64 t; cvta.to.shared.u64 t, %1; cvt.u32.u64 %0, t; }" : "=r"(a) : "l"(p));
    return a;
}
#define CP_ASYNC16(dst_u32, src_ptr) \
    asm volatile("cp.async.cg.shared.global [%0], [%1], 16;" :: "r"(dst_u32), "l"(src_ptr))
#define CP_COMMIT() asm volatile("cp.async.commit_group;")
#define CP_WAIT0() asm volatile("cp.async.wait_group 0;")
#define CP_WAIT1() asm volatile("cp.async.wait_group 1;")

// ---------------- K0a: fp16 B = W2^T image, [n][slot(k)] --------------------
__global__ void __launch_bounds__(256) k_prepB(const float* __restrict__ eW2) {
    int i = blockIdx.x * 256 + threadIdx.x; // 131072 total
    int k = i >> 10;
    int n = i & 1023;
    g_Bh[n * 128 + kslot(k)] = __float2half_rn(eW2[k * 1024 + n]);
}

// ---------------- K0b: fp16 GRU weights + folded W1 -------------------------
__global__ void __launch_bounds__(256) k_prepW(const float* __restrict__ W_hh,
                                               const float* __restrict__ root,
                                               const float* __restrict__ W_ih,
                                               const float* __restrict__ eW1,
                                               const float* __restrict__ eb1,
                                               const float* __restrict__ bn2_g,
                                               const float* __restrict__ bn2_b) {
    int tid = threadIdx.x;
    for (int i = tid; i < 128 * 32; i += 256) {
        int n = i >> 5, k = i & 31;
        float v = (n < 96) ? W_hh[n * 32 + k] : root[k * 32 + (n - 96)];
        g_Wcat[i] = __float2half_rn(v);
    }
    for (int i = tid; i < 96 * 32; i += 256)
        g_Wih[i] = __float2half_rn(W_ih[i]);
    // W1' [n][k]: eW1 is [16][128]; fold BN scale s into columns
    for (int i = tid; i < 128 * 16; i += 256) {
        int n = i >> 4, k = i & 15;
        float s = bn2_g[n] * rsqrtf(1.f + EPS_BN);
        g_W1h[i] = __float2half_rn(eW1[k * EH + n] * s);
    }
    if (tid < 128) {
        float s = bn2_g[tid] * rsqrtf(1.f + EPS_BN);
        g_b1f[tid] = eb1[tid] * s + bn2_b[tid];
    }
}

// ---------------- K1: h = relu(bn(x @ proj_W + proj_b)); zero g_agg ---------
__global__ void __launch_bounds__(256) k_proj(const float* __restrict__ x,
                                              const float* __restrict__ W,
                                              const float* __restrict__ b,
                                              const float* __restrict__ g,
                                              const float* __restrict__ bb) {
    __shared__ float Ws[DIN * D];
    int tid = threadIdx.x;
    for (int i = tid; i < DIN * D; i += 256) Ws[i] = W[i];
    __syncthreads();
    int lane = tid & 31;
    int node = blockIdx.x * 8 + (tid >> 5);
    if (node >= N_NODES) return;
    float x0 = x[node * DIN + lane];
    float x1 = x[node * DIN + 32 + lane];
    float acc = 0.f;
#pragma unroll
    for (int i = 0; i < 32; i++) {
        acc = fmaf(__shfl_sync(0xffffffffu, x0, i), Ws[i * D + lane], acc);
        acc = fmaf(__shfl_sync(0xffffffffu, x1, i), Ws[(32 + i) * D + lane], acc);
    }
    float s = g[lane] * rsqrtf(1.f + EPS_BN);
    float v = (acc + b[lane]) * s + bb[lane];
    g_h[node * D + lane] = fmaxf(v, 0.f);
    g_agg[node * D + lane] = 0.f;
}

// ---------------- K3: fused eh-MMA + theta GEMM -----------------------------
// Block: M=128 edges x full N=1024 (8 panels of 128). K=128 resident, k-permuted.
#define A_LDH 136
#define B_LDH 136
#define TH_AS 0                                 // A staging, then output staging
#define TH_B0 (128 * A_LDH * 2)                 // 34816
#define TH_B1 (TH_B0 + 128 * B_LDH * 2)         // 69632
#define TH_BIAS (TH_B1 + 128 * B_LDH * 2)       // 104448
#define TH_EA (TH_BIAS + 4096)                  // 108544: ea fp16 [128][24]
#define TH_W1 (TH_EA + 6144)                    // 114688: W1' fp16 [128][24]
#define TH_B1F (TH_W1 + 6144)                   // 120832: folded bias fp32[128]
#define TH_SMEM_TOTAL (TH_B1F + 512)            // 121344

__global__ void __launch_bounds__(256) k_theta(const float* __restrict__ eb2,
                                               const float* __restrict__ ea) {
    extern __shared__ char smem[];
    __half* As = reinterpret_cast<__half*>(smem + TH_AS);
    uint32_t* Stg = reinterpret_cast<uint32_t*>(smem + TH_AS); // reused after A consumed
    float* biass = reinterpret_cast<float*>(smem + TH_BIAS);
    __half* ea16 = reinterpret_cast<__half*>(smem + TH_EA);
    __half* w1s = reinterpret_cast<__half*>(smem + TH_W1);
    float* b1s = reinterpret_cast<float*>(smem + TH_B1F);
    const int tid = threadIdx.x, warp = tid >> 5, lane = tid & 31;
    const int m0 = blockIdx.x * 128;
    const uint32_t sb = smem_u32(smem);

    // issue cp.async: panel0 -> B0 (group0), panel1 -> B1 (group1)
    {
        const char* src = reinterpret_cast<const char*>(g_Bh);
#pragma unroll
        for (int it = 0; it < 8; it++) {
            int idx = it * 256 + tid;
            int row = idx >> 4, q = idx & 15;
            CP_ASYNC16(sb + TH_B0 + row * (B_LDH * 2) + q * 16, src + idx * 16);
        }
        CP_COMMIT();
#pragma unroll
        for (int it = 0; it < 8; it++) {
            int idx = it * 256 + tid;
            int row = idx >> 4, q = idx & 15;
            CP_ASYNC16(sb + TH_B1 + row * (B_LDH * 2) + q * 16, src + 32768 + idx * 16);
        }
        CP_COMMIT();
    }

    for (int i = tid; i < 1024; i += 256) biass[i] = eb2[i];

    // stage ea (128x16 fp32 -> fp16) and W1' (128x16) into smem, pitch 24
    {
        int row = tid >> 1, half8 = tid & 1;           // 2 threads per row
        float4 v0 = *reinterpret_cast<const float4*>(&ea[(size_t)(m0 + row) * EIN + half8 * 8]);
        float4 v1 = *reinterpret_cast<const float4*>(&ea[(size_t)(m0 + row) * EIN + half8 * 8 + 4]);
        __half2 p0 = __floats2half2_rn(v0.x, v0.y);
        __half2 p1 = __floats2half2_rn(v0.z, v0.w);
        __half2 p2 = __floats2half2_rn(v1.x, v1.y);
        __half2 p3 = __floats2half2_rn(v1.z, v1.w);
        uint32_t* dst = reinterpret_cast<uint32_t*>(&ea16[row * 24 + half8 * 8]);
        dst[0] = *reinterpret_cast<uint32_t*>(&p0);
        dst[1] = *reinterpret_cast<uint32_t*>(&p1);
        dst[2] = *reinterpret_cast<uint32_t*>(&p2);
        dst[3] = *reinterpret_cast<uint32_t*>(&p3);
    }
    for (int i = tid; i < 128 * 8; i += 256) {         // W1' as uint32 pairs
        int n = i >> 3, q = i & 7;
        reinterpret_cast<uint32_t*>(&w1s[n * 24])[q] =
            reinterpret_cast<const uint32_t*>(&g_W1h[n * 16])[q];
    }
    if (tid < 128) b1s[tid] = g_b1f[tid];
    __syncthreads();

    const int wm = (warp & 3) * 32;
    const int wn = (warp >> 2) * 64;
    const int lq = lane >> 2;
    const int lr = lane & 3;

    // eh pass: A = relu(ea @ W1' + b1'), K=16, into c0 frags
    {
        float c0[2][8][4];
#pragma unroll
        for (int mt = 0; mt < 2; mt++)
#pragma unroll
            for (int nt = 0; nt < 8; nt++)
#pragma unroll
                for (int i = 0; i < 4; i++) c0[mt][nt][i] = 0.f;
        uint32_t a[2][4];
#pragma unroll
        for (int mt = 0; mt < 2; mt++) {
            int r = wm + mt * 16 + lq;
            a[mt][0] = *reinterpret_cast<const uint32_t*>(&ea16[r * 24 + lr * 2]);
            a[mt][1] = *reinterpret_cast<const uint32_t*>(&ea16[(r + 8) * 24 + lr * 2]);
            a[mt][2] = *reinterpret_cast<const uint32_t*>(&ea16[r * 24 + lr * 2 + 8]);
            a[mt][3] = *reinterpret_cast<const uint32_t*>(&ea16[(r + 8) * 24 + lr * 2 + 8]);
        }
#pragma unroll
        for (int nt = 0; nt < 8; nt++) {
            int n = wn + nt * 8 + lq;
            uint32_t b0 = *reinterpret_cast<const uint32_t*>(&w1s[n * 24 + lr * 2]);
            uint32_t b1 = *reinterpret_cast<const uint32_t*>(&w1s[n * 24 + lr * 2 + 8]);
            mma_f16_16x8x16(c0[0][nt], a[0], b0, b1);
            mma_f16_16x8x16(c0[1][nt], a[1], b0, b1);
        }
        // relu(+bias), pack into As (k-permuted)
#pragma unroll
        for (int mt = 0; mt < 2; mt++) {
#pragma unroll
            for (int nt = 0; nt < 8; nt++) {
                int rowl = wm + mt * 16 + lq;
                int col = wn + nt * 8 + lr * 2;
                int sbase = ((col >> 4) << 4) + (((col >> 3) & 1) << 1) + (((col & 7) >> 1) << 2);
                float bb0 = b1s[col], bb1 = b1s[col + 1];
                float v0 = fmaxf(c0[mt][nt][0] + bb0, 0.f);
                float v1 = fmaxf(c0[mt][nt][1] + bb1, 0.f);
                float v2 = fmaxf(c0[mt][nt][2] + bb0, 0.f);
                float v3 = fmaxf(c0[mt][nt][3] + bb1, 0.f);
                __half2 h0 = __floats2half2_rn(v0, v1);
                __half2 h1 = __floats2half2_rn(v2, v3);
                *reinterpret_cast<uint32_t*>(&As[rowl * A_LDH + sbase]) =
                    *reinterpret_cast<uint32_t*>(&h0);
                *reinterpret_cast<uint32_t*>(&As[(rowl + 8) * A_LDH + sbase]) =
                    *reinterpret_cast<uint32_t*>(&h1);
            }
        }
    }
    __syncthreads();

    // hoist ALL A fragments into registers (reused across the 8 panels)
    uint32_t aF[8][2][4];
#pragma unroll
    for (int ks = 0; ks < 8; ks++) {
        int koff = ks * 16 + lr * 4;
#pragma unroll
        for (int mt = 0; mt < 2; mt++) {
            int r = wm + mt * 16 + lq;
            uint2 ua = *reinterpret_cast<const uint2*>(&As[r * A_LDH + koff]);
            uint2 ub = *reinterpret_cast<const uint2*>(&As[(r + 8) * A_LDH + koff]);
            aF[ks][mt][0] = ua.x; aF[ks][mt][2] = ua.y;
            aF[ks][mt][1] = ub.x; aF[ks][mt][3] = ub.y;
        }
    }
    CP_WAIT1();        // panel0 resident
    __syncthreads();

#pragma unroll 1
    for (int p = 0; p < 8; p++) {
        const __half* Bs = reinterpret_cast<const __half*>(smem + ((p & 1) ? TH_B1 : TH_B0));

        float c[2][8][4];
#pragma unroll
        for (int mt = 0; mt < 2; mt++)
#pragma unroll
            for (int nt = 0; nt < 8; nt++)
#pragma unroll
                for (int i = 0; i < 4; i++) c[mt][nt][i] = 0.f;

#pragma unroll
        for (int ks = 0; ks < 8; ks++) {
            int koff = ks * 16 + lr * 4;
#pragma unroll
            for (int nt = 0; nt < 8; nt++) {
                int n = wn + nt * 8 + lq;
                uint2 vb = *reinterpret_cast<const uint2*>(&Bs[n * B_LDH + koff]);
                mma_f16_16x8x16(c[0][nt], aF[ks][0], vb.x, vb.y);
                mma_f16_16x8x16(c[1][nt], aF[ks][1], vb.x, vb.y);
            }
        }
        __syncthreads(); // MMA(p) done by all; prev copy-out done by all

        // prefetch panel p+2 into the buffer just freed
        if (p < 6) {
            uint32_t dstb = sb + ((p & 1) ? TH_B1 : TH_B0);
            const char* src = reinterpret_cast<const char*>(g_Bh) + (size_t)(p + 2) * 32768;
#pragma unroll
            for (int it = 0; it < 8; it++) {
                int idx = it * 256 + tid;
                int row = idx >> 4, q = idx & 15;
                CP_ASYNC16(dstb + row * (B_LDH * 2) + q * 16, src + idx * 16);
            }
            CP_COMMIT();
        }

        // stage: bias add + fp16 pack -> conflict-free pitch-68 smem
#pragma unroll
        for (int mt = 0; mt < 2; mt++) {
#pragma unroll
            for (int nt = 0; nt < 8; nt++) {
                int rowl = wm + mt * 16 + lq;
                int col = wn + nt * 8 + lr * 2;
                float bv0 = biass[p * 128 + col], bv1 = biass[p * 128 + col + 1];
                __half2 h0 = __floats2half2_rn(c[mt][nt][0] + bv0, c[mt][nt][1] + bv1);
                __half2 h1 = __floats2half2_rn(c[mt][nt][2] + bv0, c[mt][nt][3] + bv1);
                Stg[rowl * 68 + (col >> 1)] = *reinterpret_cast<uint32_t*>(&h0);
                Stg[(rowl + 8) * 68 + (col >> 1)] = *reinterpret_cast<uint32_t*>(&h1);
            }
        }

        if (p < 6) CP_WAIT1();
        else if (p == 6) CP_WAIT0();
        __syncthreads();

        // coalesced copy-out: 128 rows x 256B
#pragma unroll
        for (int it = 0; it < 8; it++) {
            int idx = it * 256 + tid;
            int row = idx >> 4, q = idx & 15;
            uint4 u = *reinterpret_cast<const uint4*>(&Stg[row * 68 + q * 4]);
            reinterpret_cast<uint4*>(g_theta)[(size_t)(m0 + row) * 128 + p * 16 + q] = u;
        }
    }
}

// ---------------- K5: msg = h[src] @ theta_e ; atomic scatter ---------------
__global__ void __launch_bounds__(256) k_msg(const int* __restrict__ ei) {
    int gw = (blockIdx.x * blockDim.x + threadIdx.x) >> 5;
    if (gw >= N_EDGES) return;
    int lane = threadIdx.x & 31;
    int src = __ldg(&ei[gw]);
    int dst = __ldg(&ei[N_EDGES + gw]);
    float hv = g_h[src * D + lane];
    const uint2* th = reinterpret_cast<const uint2*>(g_theta + (size_t)gw * 512);
    const int q = lane >> 3;
    const int c8 = lane & 7;
    float a0 = 0.f, a1 = 0.f, a2 = 0.f, a3 = 0.f;
#pragma unroll
    for (int it = 0; it < 8; it++) {
        int r = it * 4 + q;
        uint2 u = __ldcs(&th[r * 8 + c8]);
        float hr = __shfl_sync(0xffffffffu, hv, r);
        float2 f01 = __half22float2(*reinterpret_cast<const __half2*>(&u.x));
        float2 f23 = __half22float2(*reinterpret_cast<const __half2*>(&u.y));
        a0 = fmaf(hr, f01.x, a0);
        a1 = fmaf(hr, f01.y, a1);
        a2 = fmaf(hr, f23.x, a2);
        a3 = fmaf(hr, f23.y, a3);
    }
    a0 += __shfl_xor_sync(0xffffffffu, a0, 8);
    a1 += __shfl_xor_sync(0xffffffffu, a1, 8);
    a2 += __shfl_xor_sync(0xffffffffu, a2, 8);
    a3 += __shfl_xor_sync(0xffffffffu, a3, 8);
    a0 += __shfl_xor_sync(0xffffffffu, a0, 16);
    a1 += __shfl_xor_sync(0xffffffffu, a1, 16);
    a2 += __shfl_xor_sync(0xffffffffu, a2, 16);
    a3 += __shfl_xor_sync(0xffffffffu, a3, 16);
    if (lane < 8) {
        float* dp = &g_agg[dst * D + c8 * 4];
        atomicAdd(dp + 0, a0);
        atomicAdd(dp + 1, a1);
        atomicAdd(dp + 2, a2);
        atomicAdd(dp + 3, a3);
    }
}

// ---------------- K6: conv + relu + GRU via HMMA, 128 nodes/block -----------
#define UP_H16 0                         // half [128][36]
#define UP_M16 (UP_H16 + 9216)           // half [128][36]
#define UP_W1  (UP_M16 + 9216)           // half [128][36]  (W_hh | root^T)
#define UP_W2  (UP_W1 + 9216)            // half [96][36]   (W_ih)
#define UP_HF  (UP_W2 + 6912)            // float [128][36]
#define UP_BIH (UP_HF + 18432)           // float [96]
#define UP_BHH (UP_BIH + 384)            // float [96]
#define UP_CB  (UP_BHH + 384)            // float [32]
#define UP_SMEM_TOTAL (UP_CB + 128)      // 53888

__global__ void __launch_bounds__(256) k_update(const float* __restrict__ cb,
                                                const float* __restrict__ b_ih,
                                                const float* __restrict__ b_hh,
                                                float* __restrict__ out,
                                                int write_out) {
    extern __shared__ char smem[];
    __half* h16 = reinterpret_cast<__half*>(smem + UP_H16);
    __half* m16 = reinterpret_cast<__half*>(smem + UP_M16);
    __half* w1 = reinterpret_cast<__half*>(smem + UP_W1);
    __half* w2 = reinterpret_cast<__half*>(smem + UP_W2);
    float* hf = reinterpret_cast<float*>(smem + UP_HF);
    float* sbih = reinterpret_cast<float*>(smem + UP_BIH);
    float* sbhh = reinterpret_cast<float*>(smem + UP_BHH);
    float* scb = reinterpret_cast<float*>(smem + UP_CB);
    const int tid = threadIdx.x, warp = tid >> 5, lane = tid & 31;
    const int lq = lane >> 2, lr = lane & 3;
    const int node0 = blockIdx.x * 128;
    const int wm = warp * 16;

    for (int i = tid; i < 128 * 32; i += 256) {
        int n = i >> 5, k = i & 31;
        w1[n * 36 + k] = g_Wcat[i];
    }
    for (int i = tid; i < 96 * 32; i += 256) {
        int n = i >> 5, k = i & 31;
        w2[n * 36 + k] = g_Wih[i];
    }
    if (tid < 96) { sbih[tid] = b_ih[tid]; sbhh[tid] = b_hh[tid]; }
    if (tid < 32) scb[tid] = cb[tid];

#pragma unroll
    for (int it = 0; it < 4; it++) {
        int idx = it * 256 + tid;
        int row = idx >> 3;
        int c4 = (idx & 7) << 2;
        int node = node0 + row;
        float4 v = make_float4(0.f, 0.f, 0.f, 0.f);
        if (node < N_NODES)
            v = *reinterpret_cast<const float4*>(&g_h[node * D + c4]);
        *reinterpret_cast<float4*>(&hf[row * 36 + c4]) = v;
        __half2 p0 = __floats2half2_rn(v.x, v.y);
        __half2 p1 = __floats2half2_rn(v.z, v.w);
        uint2 u = make_uint2(*reinterpret_cast<uint32_t*>(&p0),
                             *reinterpret_cast<uint32_t*>(&p1));
        *reinterpret_cast<uint2*>(&h16[row * 36 + c4]) = u;
    }
    __syncthreads();

    float c1[16][4];
#pragma unroll
    for (int nt = 0; nt < 16; nt++)
#pragma unroll
        for (int i = 0; i < 4; i++) c1[nt][i] = 0.f;
#pragma unroll
    for (int ks = 0; ks < 2; ks++) {
        int kb = ks * 16 + lr * 2;
        uint32_t a[4];
        a[0] = *reinterpret_cast<const uint32_t*>(&h16[(wm + lq) * 36 + kb]);
        a[2] = *reinterpret_cast<const uint32_t*>(&h16[(wm + lq) * 36 + kb + 8]);
        a[1] = *reinterpret_cast<const uint32_t*>(&h16[(wm + lq + 8) * 36 + kb]);
        a[3] = *reinterpret_cast<const uint32_t*>(&h16[(wm + lq + 8) * 36 + kb + 8]);
#pragma unroll
        for (int nt = 0; nt < 16; nt++) {
            int n = nt * 8 + lq;
            uint32_t b0 = *reinterpret_cast<const uint32_t*>(&w1[n * 36 + kb]);
            uint32_t b1 = *reinterpret_cast<const uint32_t*>(&w1[n * 36 + kb + 8]);
            mma_f16_16x8x16(c1[nt], a, b0, b1);
        }
    }

    int rowA = wm + lq, rowB = wm + lq + 8;
    int nodeA = node0 + rowA, nodeB = node0 + rowB;
#pragma unroll
    for (int nt = 0; nt < 4; nt++) {
        int jp = nt * 8 + lr * 2;
        float cb0 = scb[jp], cb1 = scb[jp + 1];
        float2 agA = make_float2(0.f, 0.f), agB = make_float2(0.f, 0.f);
        if (nodeA < N_NODES) agA = *reinterpret_cast<const float2*>(&g_agg[nodeA * D + jp]);
        if (nodeB < N_NODES) agB = *reinterpret_cast<const float2*>(&g_agg[nodeB * D + jp]);
        float m0v = fmaxf(c1[12 + nt][0] + agA.x + cb0, 0.f);
        float m1v = fmaxf(c1[12 + nt][1] + agA.y + cb1, 0.f);
        float m2v = fmaxf(c1[12 + nt][2] + agB.x + cb0, 0.f);
        float m3v = fmaxf(c1[12 + nt][3] + agB.y + cb1, 0.f);
        __half2 hA = __floats2half2_rn(m0v, m1v);
        __half2 hB = __floats2half2_rn(m2v, m3v);
        *reinterpret_cast<uint32_t*>(&m16[rowA * 36 + jp]) =
            *reinterpret_cast<uint32_t*>(&hA);
        *reinterpret_cast<uint32_t*>(&m16[rowB * 36 + jp]) =
            *reinterpret_cast<uint32_t*>(&hB);
    }
    __syncthreads();

    float c2[12][4];
#pragma unroll
    for (int nt = 0; nt < 12; nt++)
#pragma unroll
        for (int i = 0; i < 4; i++) c2[nt][i] = 0.f;
#pragma unroll
    for (int ks = 0; ks < 2; ks++) {
        int kb = ks * 16 + lr * 2;
        uint32_t a[4];
        a[0] = *reinterpret_cast<const uint32_t*>(&m16[(wm + lq) * 36 + kb]);
        a[2] = *reinterpret_cast<const uint32_t*>(&m16[(wm + lq) * 36 + kb + 8]);
        a[1] = *reinterpret_cast<const uint32_t*>(&m16[(wm + lq + 8) * 36 + kb]);
        a[3] = *reinterpret_cast<const uint32_t*>(&m16[(wm + lq + 8) * 36 + kb + 8]);
#pragma unroll
        for (int nt = 0; nt < 12; nt++) {
            int n = nt * 8 + lq;
            uint32_t b0 = *reinterpret_cast<const uint32_t*>(&w2[n * 36 + kb]);
            uint32_t b1 = *reinterpret_cast<const uint32_t*>(&w2[n * 36 + kb + 8]);
            mma_f16_16x8x16(c2[nt], a, b0, b1);
        }
    }

#pragma unroll
    for (int nt = 0; nt < 4; nt++) {
        int jp = nt * 8 + lr * 2;
#pragma unroll
        for (int hrow = 0; hrow < 2; hrow++) {
            int node = hrow ? nodeB : nodeA;
            if (node >= N_NODES) continue;
            int rl = hrow ? rowB : rowA;
            float hn0, hn1;
            {
                int ci = 2 * hrow;
                float gr0 = c2[nt][ci] + sbih[jp] + c1[nt][ci] + sbhh[jp];
                float gr1 = c2[nt][ci + 1] + sbih[jp + 1] + c1[nt][ci + 1] + sbhh[jp + 1];
                float gz0 = c2[4 + nt][ci] + sbih[32 + jp] + c1[4 + nt][ci] + sbhh[32 + jp];
                float gz1 = c2[4 + nt][ci + 1] + sbih[33 + jp] + c1[4 + nt][ci + 1] + sbhh[33 + jp];
                float r0 = 1.f / (1.f + expf(-gr0));
                float r1 = 1.f / (1.f + expf(-gr1));
                float z0 = 1.f / (1.f + expf(-gz0));
                float z1 = 1.f / (1.f + expf(-gz1));
                float gn0 = c2[8 + nt][ci] + sbih[64 + jp];
                float gn1 = c2[8 + nt][ci + 1] + sbih[65 + jp];
                float ghn0 = c1[8 + nt][ci] + sbhh[64 + jp];
                float ghn1 = c1[8 + nt][ci + 1] + sbhh[65 + jp];
                float n0 = tanhf(gn0 + r0 * ghn0);
                float n1 = tanhf(gn1 + r1 * ghn1);
                float hv0 = hf[rl * 36 + jp];
                float hv1 = hf[rl * 36 + jp + 1];
                hn0 = (1.f - z0) * n0 + z0 * hv0;
                hn1 = (1.f - z1) * n1 + z1 * hv1;
            }
            float2 hv2 = make_float2(hn0, hn1);
            *reinterpret_cast<float2*>(&g_h[node * D + jp]) = hv2;
            *reinterpret_cast<float2*>(&g_agg[node * D + jp]) = make_float2(0.f, 0.f);
            if (write_out)
                *reinterpret_cast<float2*>(&out[node * D + jp]) = hv2;
        }
    }
}

// ---------------- launch ----------------
extern "C" void kernel_launch(void* const* d_in, const int* in_sizes, int n_in,
                              void* d_out, int out_size) {
    (void)in_sizes; (void)n_in; (void)out_size;
    const float* x        = (const float*)d_in[0];
    const int*   ei       = (const int*)d_in[1];
    const float* ea       = (const float*)d_in[2];
    const float* proj_W   = (const float*)d_in[3];
    const float* proj_b   = (const float*)d_in[4];
    const float* bn1_g    = (const float*)d_in[5];
    const float* bn1_b    = (const float*)d_in[6];
    const float* eW1      = (const float*)d_in[7];
    const float* eb1      = (const float*)d_in[8];
    const float* bn2_g    = (const float*)d_in[9];
    const float* bn2_b    = (const float*)d_in[10];
    const float* eW2      = (const float*)d_in[11];
    const float* eb2      = (const float*)d_in[12];
    const float* root     = (const float*)d_in[13];
    const float* cb       = (const float*)d_in[14];
    const float* W_ih     = (const float*)d_in[15];
    const float* W_hh     = (const float*)d_in[16];
    const float* b_ih     = (const float*)d_in[17];
    const float* b_hh     = (const float*)d_in[18];
    float* out = (float*)d_out;

    static int attr_set = 0;
    if (!attr_set) {
        cudaFuncSetAttribute(k_theta, cudaFuncAttributeMaxDynamicSharedMemorySize,
                             TH_SMEM_TOTAL);
        cudaFuncSetAttribute(k_update, cudaFuncAttributeMaxDynamicSharedMemorySize,
                             UP_SMEM_TOTAL);
        attr_set = 1;
    }

    k_prepB<<<512, 256>>>(eW2);                                       // 1
    k_prepW<<<1, 256>>>(W_hh, root, W_ih, eW1, eb1, bn2_g, bn2_b);    // 2
    k_proj<<<N_NODES / 8, 256>>>(x, proj_W, proj_b, bn1_g, bn1_b);    // 3
    k_theta<<<N_EDGES / 128, 256, TH_SMEM_TOTAL>>>(eb2, ea);          // 4 <- profiled

    for (int s = 0; s < STEPS; s++) {
        k_msg<<<(N_EDGES * 32) / 256, 256>>>(ei);
        k_update<<<(N_NODES + 127) / 128, 256, UP_SMEM_TOTAL>>>(
            cb, b_ih, b_hh, out, s == STEPS - 1 ? 1 : 0);
    }
}

// round 8
// speedup vs baseline: 4.5346x; 1.1679x over previous
#include <cuda_runtime.h>
#include <cuda_fp16.h>
#include <cstdint>
#include <math.h>

#define N_NODES 40000
#define N_EDGES 160000
#define DIN 64
#define D 32
#define EIN 16
#define EH 128
#define STEPS 3
#define EPS_BN 1e-5f

// ---------------- device scratch (no allocation allowed) ----------------
__device__ float g_h[N_NODES * D];                  // node features / GRU hidden
__device__ uint32_t g_theta[(size_t)N_EDGES * 512]; // per-edge mats, fp16 pairs (327 MB)
__device__ float g_agg[N_NODES * D];                // scatter-add accumulator
__device__ uint2 g_Bh[8 * 4096];                    // fp16 W2^T, fragment-native (256 KB)
__device__ __half g_Wcat[128 * 32];                 // [W_hh(96) | root^T(32)] fp16
__device__ __half g_Wih[96 * 32];                   // W_ih fp16
__device__ __half g_W1h[128 * 16];                  // fp16 W1' = W1 * bn-scale, [n][k]
__device__ float g_b1f[128];                        // folded edge-hidden bias

__device__ __forceinline__ void mma_f16_16x8x16(float c[4], const uint32_t a[4],
                                                uint32_t b0, uint32_t b1) {
    asm volatile(
        "mma.sync.aligned.m16n8k16.row.col.f32.f16.f16.f32 "
        "{%0,%1,%2,%3}, {%4,%5,%6,%7}, {%8,%9}, {%0,%1,%2,%3};"
        : "+f"(c[0]), "+f"(c[1]), "+f"(c[2]), "+f"(c[3])
        : "r"(a[0]), "r"(a[1]), "r"(a[2]), "r"(a[3]), "r"(b0), "r"(b1));
}

__device__ __forceinline__ uint32_t smem_u32(const void* p) {
    uint32_t a;
    asm("{ .reg .u64 t; cvta.to.shared.u64 t, %1; cvt.u32.u64 %0, t; }" : "=r"(a) : "l"(p));
    return a;
}
#define CP_ASYNC16(dst_u32, src_ptr) \
    asm volatile("cp.async.cg.shared.global [%0], [%1], 16;" :: "r"(dst_u32), "l"(src_ptr))
#define CP_COMMIT() asm volatile("cp.async.commit_group;")
#define CP_WAIT0() asm volatile("cp.async.wait_group 0;")
#define CP_WAIT1() asm volatile("cp.async.wait_group 1;")
#define BAR_PAIR(id) asm volatile("bar.sync %0, %1;" :: "r"(id), "r"(64) : "memory")

__device__ __forceinline__ uint32_t pack_h2(float a, float b) {
    __half2 h = __floats2half2_rn(a, b);
    return *reinterpret_cast<uint32_t*>(&h);
}

// ---------------- K0a: B = W2^T in MMA-fragment-native order ----------------
// uint2 index j: p=j>>12, ks=(j>>9)&7, ntg=(j>>5)&15, lane=j&31 (lq=lane>>2,lr=lane&3)
// value: n = p*128+ntg*8+lq ; k0 = ks*16+lr*2 ; x={B[n][k0],B[n][k0+1]} y={B[n][k0+8],+9}
__global__ void __launch_bounds__(256) k_prepB(const float* __restrict__ eW2) {
    int j = blockIdx.x * 256 + threadIdx.x; // 32768 total
    int p = j >> 12, r = j & 4095;
    int ks = r >> 9, ntg = (r >> 5) & 15, lane = r & 31;
    int lq = lane >> 2, lr = lane & 3;
    int n = p * 128 + ntg * 8 + lq;
    int k0 = ks * 16 + lr * 2;
    uint2 v;
    v.x = pack_h2(eW2[(size_t)k0 * 1024 + n], eW2[(size_t)(k0 + 1) * 1024 + n]);
    v.y = pack_h2(eW2[(size_t)(k0 + 8) * 1024 + n], eW2[(size_t)(k0 + 9) * 1024 + n]);
    g_Bh[j] = v;
}

// ---------------- K0b: fp16 GRU weights + folded W1 -------------------------
__global__ void __launch_bounds__(256) k_prepW(const float* __restrict__ W_hh,
                                               const float* __restrict__ root,
                                               const float* __restrict__ W_ih,
                                               const float* __restrict__ eW1,
                                               const float* __restrict__ eb1,
                                               const float* __restrict__ bn2_g,
                                               const float* __restrict__ bn2_b) {
    int tid = threadIdx.x;
    for (int i = tid; i < 128 * 32; i += 256) {
        int n = i >> 5, k = i & 31;
        float v = (n < 96) ? W_hh[n * 32 + k] : root[k * 32 + (n - 96)];
        g_Wcat[i] = __float2half_rn(v);
    }
    for (int i = tid; i < 96 * 32; i += 256)
        g_Wih[i] = __float2half_rn(W_ih[i]);
    for (int i = tid; i < 128 * 16; i += 256) {
        int n = i >> 4, k = i & 15;
        float s = bn2_g[n] * rsqrtf(1.f + EPS_BN);
        g_W1h[i] = __float2half_rn(eW1[k * EH + n] * s);
    }
    if (tid < 128) {
        float s = bn2_g[tid] * rsqrtf(1.f + EPS_BN);
        g_b1f[tid] = eb1[tid] * s + bn2_b[tid];
    }
}

// ---------------- K1: h = relu(bn(x @ proj_W + proj_b)); zero g_agg ---------
__global__ void __launch_bounds__(256) k_proj(const float* __restrict__ x,
                                              const float* __restrict__ W,
                                              const float* __restrict__ b,
                                              const float* __restrict__ g,
                                              const float* __restrict__ bb) {
    __shared__ float Ws[DIN * D];
    int tid = threadIdx.x;
    for (int i = tid; i < DIN * D; i += 256) Ws[i] = W[i];
    __syncthreads();
    int lane = tid & 31;
    int node = blockIdx.x * 8 + (tid >> 5);
    if (node >= N_NODES) return;
    float x0 = x[node * DIN + lane];
    float x1 = x[node * DIN + 32 + lane];
    float acc = 0.f;
#pragma unroll
    for (int i = 0; i < 32; i++) {
        acc = fmaf(__shfl_sync(0xffffffffu, x0, i), Ws[i * D + lane], acc);
        acc = fmaf(__shfl_sync(0xffffffffu, x1, i), Ws[(32 + i) * D + lane], acc);
    }
    float s = g[lane] * rsqrtf(1.f + EPS_BN);
    float v = (acc + b[lane]) * s + bb[lane];
    g_h[node * D + lane] = fmaxf(v, 0.f);
    g_agg[node * D + lane] = 0.f;
}

// ---------------- K3: fused eh-MMA + theta GEMM v4 (2 blocks/SM) ------------
// smem: AF (A frags, 32K) | B0 32K | B1 32K | stage 16K (prologue overlaps stage)
#define TH_AF 0
#define TH_B0 32768
#define TH_B1 65536
#define TH_STG 98304
#define TH_EA 98304                  // prologue: ea fp16 [128][24]
#define TH_W1 104448                 // prologue: W1' fp16 [128][24]
#define TH_B1F 110592                // prologue: folded bias fp32[128]
#define TH_SMEM_TOTAL 114688

__global__ void __launch_bounds__(256, 2) k_theta(const float* __restrict__ eb2,
                                                  const float* __restrict__ ea) {
    extern __shared__ char smem[];
    uint4* AF = reinterpret_cast<uint4*>(smem + TH_AF);
    uint32_t* stg = reinterpret_cast<uint32_t*>(smem + TH_STG);
    __half* ea16 = reinterpret_cast<__half*>(smem + TH_EA);
    __half* w1s = reinterpret_cast<__half*>(smem + TH_W1);
    float* b1s = reinterpret_cast<float*>(smem + TH_B1F);
    const int tid = threadIdx.x, warp = tid >> 5, lane = tid & 31;
    const int lq = lane >> 2, lr = lane & 3;
    const int m0 = blockIdx.x * 128;
    const uint32_t sb = smem_u32(smem);
    const int wg = warp & 3;           // m-pair id (rows wg*32..wg*32+31)
    const int wh = warp >> 2;          // n-half (0: cols 0-63, 1: 64-127)
    const int wn = wh * 64;

    // issue cp.async: panel0 -> B0 (g0), panel1 -> B1 (g1)
    {
        const char* src = reinterpret_cast<const char*>(g_Bh);
#pragma unroll
        for (int it = 0; it < 8; it++) {
            int idx = it * 256 + tid;
            CP_ASYNC16(sb + TH_B0 + idx * 16, src + idx * 16);
        }
        CP_COMMIT();
#pragma unroll
        for (int it = 0; it < 8; it++) {
            int idx = it * 256 + tid;
            CP_ASYNC16(sb + TH_B1 + idx * 16, src + 32768 + idx * 16);
        }
        CP_COMMIT();
    }

    // prologue: stage ea (fp32 -> fp16) and W1' into smem (pitch 24)
    {
        int row = tid >> 1, half8 = tid & 1;
        float4 v0 = *reinterpret_cast<const float4*>(&ea[(size_t)(m0 + row) * EIN + half8 * 8]);
        float4 v1 = *reinterpret_cast<const float4*>(&ea[(size_t)(m0 + row) * EIN + half8 * 8 + 4]);
        uint32_t* dst = reinterpret_cast<uint32_t*>(&ea16[row * 24 + half8 * 8]);
        dst[0] = pack_h2(v0.x, v0.y);
        dst[1] = pack_h2(v0.z, v0.w);
        dst[2] = pack_h2(v1.x, v1.y);
        dst[3] = pack_h2(v1.z, v1.w);
    }
    for (int i = tid; i < 128 * 8; i += 256) {
        int n = i >> 3, q = i & 7;
        reinterpret_cast<uint32_t*>(&w1s[n * 24])[q] =
            reinterpret_cast<const uint32_t*>(&g_W1h[n * 16])[q];
    }
    if (tid < 128) b1s[tid] = g_b1f[tid];
    __syncthreads();

    // eh pass: A = relu(ea @ W1' + b1'), K=16; write fragment-native AF
    {
        float c0[2][8][4];
#pragma unroll
        for (int mt = 0; mt < 2; mt++)
#pragma unroll
            for (int nt = 0; nt < 8; nt++)
#pragma unroll
                for (int i = 0; i < 4; i++) c0[mt][nt][i] = 0.f;
        uint32_t a[2][4];
#pragma unroll
        for (int mt = 0; mt < 2; mt++) {
            int r = wg * 32 + mt * 16 + lq;
            a[mt][0] = *reinterpret_cast<const uint32_t*>(&ea16[r * 24 + lr * 2]);
            a[mt][1] = *reinterpret_cast<const uint32_t*>(&ea16[(r + 8) * 24 + lr * 2]);
            a[mt][2] = *reinterpret_cast<const uint32_t*>(&ea16[r * 24 + lr * 2 + 8]);
            a[mt][3] = *reinterpret_cast<const uint32_t*>(&ea16[(r + 8) * 24 + lr * 2 + 8]);
        }
#pragma unroll
        for (int nt = 0; nt < 8; nt++) {
            int n = wn + nt * 8 + lq;
            uint32_t b0 = *reinterpret_cast<const uint32_t*>(&w1s[n * 24 + lr * 2]);
            uint32_t b1 = *reinterpret_cast<const uint32_t*>(&w1s[n * 24 + lr * 2 + 8]);
            mma_f16_16x8x16(c0[0][nt], a[0], b0, b1);
            mma_f16_16x8x16(c0[1][nt], a[1], b0, b1);
        }
        // relu(+bias), pack into AF: AF[(mg*8+ks)*32+lane] = {a0,a1,a2,a3}
#pragma unroll
        for (int mt = 0; mt < 2; mt++) {
#pragma unroll
            for (int t = 0; t < 4; t++) {
                int nt0 = 2 * t, nt1 = 2 * t + 1;
                int col0 = wn + nt0 * 8 + lr * 2;
                int col1 = wn + nt1 * 8 + lr * 2;
                float b00 = b1s[col0], b01 = b1s[col0 + 1];
                float b10 = b1s[col1], b11 = b1s[col1 + 1];
                uint4 u;
                u.x = pack_h2(fmaxf(c0[mt][nt0][0] + b00, 0.f), fmaxf(c0[mt][nt0][1] + b01, 0.f));
                u.y = pack_h2(fmaxf(c0[mt][nt0][2] + b00, 0.f), fmaxf(c0[mt][nt0][3] + b01, 0.f));
                u.z = pack_h2(fmaxf(c0[mt][nt1][0] + b10, 0.f), fmaxf(c0[mt][nt1][1] + b11, 0.f));
                u.w = pack_h2(fmaxf(c0[mt][nt1][2] + b10, 0.f), fmaxf(c0[mt][nt1][3] + b11, 0.f));
                int mg = wg * 2 + mt;
                int ks = wh * 4 + t;
                AF[(mg * 8 + ks) * 32 + lane] = u;
            }
        }
    }
    CP_WAIT1();        // g0 (panel 0) resident locally
    __syncthreads();   // AF visible + panel0 collective

    const int mg0 = wg * 2;
    const int pairbar = 1 + wg;

#pragma unroll 1
    for (int p = 0; p < 8; p++) {
        const uint2* Bs = reinterpret_cast<const uint2*>(smem + ((p & 1) ? TH_B1 : TH_B0));

        float c[2][8][4];
#pragma unroll
        for (int mt = 0; mt < 2; mt++)
#pragma unroll
            for (int nt = 0; nt < 8; nt++)
#pragma unroll
                for (int i = 0; i < 4; i++) c[mt][nt][i] = 0.f;

#pragma unroll
        for (int ks = 0; ks < 8; ks++) {
            uint4 ua0 = AF[(mg0 * 8 + ks) * 32 + lane];
            uint4 ua1 = AF[((mg0 + 1) * 8 + ks) * 32 + lane];
            uint32_t a0[4] = {ua0.x, ua0.y, ua0.z, ua0.w};
            uint32_t a1[4] = {ua1.x, ua1.y, ua1.z, ua1.w};
#pragma unroll
            for (int nt = 0; nt < 8; nt++) {
                uint2 vb = Bs[(ks * 16 + wh * 8 + nt) * 32 + lane];
                mma_f16_16x8x16(c[0][nt], a0, vb.x, vb.y);
                mma_f16_16x8x16(c[1][nt], a1, vb.x, vb.y);
            }
        }

        if (p < 7) CP_WAIT0();   // panel p+1 landed (thread-local)
        __syncthreads();         // collective: B[p&1] free, panel p+1 visible

        // prefetch panel p+2 into the buffer just freed
        if (p < 6) {
            uint32_t dstb = sb + ((p & 1) ? TH_B1 : TH_B0);
            const char* src = reinterpret_cast<const char*>(g_Bh) + (size_t)(p + 2) * 32768;
#pragma unroll
            for (int it = 0; it < 8; it++) {
                int idx = it * 256 + tid;
                CP_ASYNC16(dstb + idx * 16, src + idx * 16);
            }
            CP_COMMIT();
        }

        // epilogue: two mt rounds, pair-local staging + coalesced copy-out
#pragma unroll
        for (int mt = 0; mt < 2; mt++) {
#pragma unroll
            for (int nt = 0; nt < 8; nt++) {
                int col = wn + nt * 8 + lr * 2;
                float2 bv = __ldg(reinterpret_cast<const float2*>(&eb2[p * 128 + col]));
                uint32_t h0 = pack_h2(c[mt][nt][0] + bv.x, c[mt][nt][1] + bv.y);
                uint32_t h1 = pack_h2(c[mt][nt][2] + bv.x, c[mt][nt][3] + bv.y);
                int cch = wh * 8 + nt;                 // chunk 0..15
                int r0 = wg * 16 + lq;
                int r1 = r0 + 8;
                stg[r0 * 64 + ((cch ^ (r0 & 15)) << 2) + lr] = h0;
                stg[r1 * 64 + ((cch ^ (r1 & 15)) << 2) + lr] = h1;
            }
            BAR_PAIR(pairbar);
            // copy-out: pair rows (16) x 16 chunks; this warp does 8 rows
#pragma unroll
            for (int i = 0; i < 4; i++) {
                int idx = i * 32 + lane;               // 0..127
                int lrow8 = idx >> 4;
                int cch = idx & 15;
                int localRow = wg * 16 + wh * 8 + lrow8;
                uint4 v = *reinterpret_cast<const uint4*>(
                    &stg[localRow * 64 + ((cch ^ (localRow & 15)) << 2)]);
                int globalRow = m0 + wg * 32 + mt * 16 + wh * 8 + lrow8;
                reinterpret_cast<uint4*>(g_theta)[(size_t)globalRow * 128 + p * 16 + cch] = v;
            }
            BAR_PAIR(pairbar);
        }
    }
}

// ---------------- K5: msg = h[src] @ theta_e ; atomic scatter ---------------
__global__ void __launch_bounds__(256) k_msg(const int* __restrict__ ei) {
    int gw = (blockIdx.x * blockDim.x + threadIdx.x) >> 5;
    if (gw >= N_EDGES) return;
    int lane = threadIdx.x & 31;
    int src = __ldg(&ei[gw]);
    int dst = __ldg(&ei[N_EDGES + gw]);
    float hv = g_h[src * D + lane];
    const uint2* th = reinterpret_cast<const uint2*>(g_theta + (size_t)gw * 512);
    const int q = lane >> 3;
    const int c8 = lane & 7;
    float a0 = 0.f, a1 = 0.f, a2 = 0.f, a3 = 0.f;
#pragma unroll
    for (int it = 0; it < 8; it++) {
        int r = it * 4 + q;
        uint2 u = __ldcs(&th[r * 8 + c8]);
        float hr = __shfl_sync(0xffffffffu, hv, r);
        float2 f01 = __half22float2(*reinterpret_cast<const __half2*>(&u.x));
        float2 f23 = __half22float2(*reinterpret_cast<const __half2*>(&u.y));
        a0 = fmaf(hr, f01.x, a0);
        a1 = fmaf(hr, f01.y, a1);
        a2 = fmaf(hr, f23.x, a2);
        a3 = fmaf(hr, f23.y, a3);
    }
    a0 += __shfl_xor_sync(0xffffffffu, a0, 8);
    a1 += __shfl_xor_sync(0xffffffffu, a1, 8);
    a2 += __shfl_xor_sync(0xffffffffu, a2, 8);
    a3 += __shfl_xor_sync(0xffffffffu, a3, 8);
    a0 += __shfl_xor_sync(0xffffffffu, a0, 16);
    a1 += __shfl_xor_sync(0xffffffffu, a1, 16);
    a2 += __shfl_xor_sync(0xffffffffu, a2, 16);
    a3 += __shfl_xor_sync(0xffffffffu, a3, 16);
    if (lane < 8) {
        float* dp = &g_agg[dst * D + c8 * 4];
        atomicAdd(dp + 0, a0);
        atomicAdd(dp + 1, a1);
        atomicAdd(dp + 2, a2);
        atomicAdd(dp + 3, a3);
    }
}

// ---------------- K6: conv + relu + GRU via HMMA, 128 nodes/block -----------
#define UP_H16 0
#define UP_M16 (UP_H16 + 9216)
#define UP_W1  (UP_M16 + 9216)
#define UP_W2  (UP_W1 + 9216)
#define UP_HF  (UP_W2 + 6912)
#define UP_BIH (UP_HF + 18432)
#define UP_BHH (UP_BIH + 384)
#define UP_CB  (UP_BHH + 384)
#define UP_SMEM_TOTAL (UP_CB + 128)

__global__ void __launch_bounds__(256) k_update(const float* __restrict__ cb,
                                                const float* __restrict__ b_ih,
                                                const float* __restrict__ b_hh,
                                                float* __restrict__ out,
                                                int write_out) {
    extern __shared__ char smem[];
    __half* h16 = reinterpret_cast<__half*>(smem + UP_H16);
    __half* m16 = reinterpret_cast<__half*>(smem + UP_M16);
    __half* w1 = reinterpret_cast<__half*>(smem + UP_W1);
    __half* w2 = reinterpret_cast<__half*>(smem + UP_W2);
    float* hf = reinterpret_cast<float*>(smem + UP_HF);
    float* sbih = reinterpret_cast<float*>(smem + UP_BIH);
    float* sbhh = reinterpret_cast<float*>(smem + UP_BHH);
    float* scb = reinterpret_cast<float*>(smem + UP_CB);
    const int tid = threadIdx.x, warp = tid >> 5, lane = tid & 31;
    const int lq = lane >> 2, lr = lane & 3;
    const int node0 = blockIdx.x * 128;
    const int wm = warp * 16;

    for (int i = tid; i < 128 * 32; i += 256) {
        int n = i >> 5, k = i & 31;
        w1[n * 36 + k] = g_Wcat[i];
    }
    for (int i = tid; i < 96 * 32; i += 256) {
        int n = i >> 5, k = i & 31;
        w2[n * 36 + k] = g_Wih[i];
    }
    if (tid < 96) { sbih[tid] = b_ih[tid]; sbhh[tid] = b_hh[tid]; }
    if (tid < 32) scb[tid] = cb[tid];

#pragma unroll
    for (int it = 0; it < 4; it++) {
        int idx = it * 256 + tid;
        int row = idx >> 3;
        int c4 = (idx & 7) << 2;
        int node = node0 + row;
        float4 v = make_float4(0.f, 0.f, 0.f, 0.f);
        if (node < N_NODES)
            v = *reinterpret_cast<const float4*>(&g_h[node * D + c4]);
        *reinterpret_cast<float4*>(&hf[row * 36 + c4]) = v;
        uint2 u = make_uint2(pack_h2(v.x, v.y), pack_h2(v.z, v.w));
        *reinterpret_cast<uint2*>(&h16[row * 36 + c4]) = u;
    }
    __syncthreads();

    float c1[16][4];
#pragma unroll
    for (int nt = 0; nt < 16; nt++)
#pragma unroll
        for (int i = 0; i < 4; i++) c1[nt][i] = 0.f;
#pragma unroll
    for (int ks = 0; ks < 2; ks++) {
        int kb = ks * 16 + lr * 2;
        uint32_t a[4];
        a[0] = *reinterpret_cast<const uint32_t*>(&h16[(wm + lq) * 36 + kb]);
        a[2] = *reinterpret_cast<const uint32_t*>(&h16[(wm + lq) * 36 + kb + 8]);
        a[1] = *reinterpret_cast<const uint32_t*>(&h16[(wm + lq + 8) * 36 + kb]);
        a[3] = *reinterpret_cast<const uint32_t*>(&h16[(wm + lq + 8) * 36 + kb + 8]);
#pragma unroll
        for (int nt = 0; nt < 16; nt++) {
            int n = nt * 8 + lq;
            uint32_t b0 = *reinterpret_cast<const uint32_t*>(&w1[n * 36 + kb]);
            uint32_t b1 = *reinterpret_cast<const uint32_t*>(&w1[n * 36 + kb + 8]);
            mma_f16_16x8x16(c1[nt], a, b0, b1);
        }
    }

    int rowA = wm + lq, rowB = wm + lq + 8;
    int nodeA = node0 + rowA, nodeB = node0 + rowB;
#pragma unroll
    for (int nt = 0; nt < 4; nt++) {
        int jp = nt * 8 + lr * 2;
        float cb0 = scb[jp], cb1 = scb[jp + 1];
        float2 agA = make_float2(0.f, 0.f), agB = make_float2(0.f, 0.f);
        if (nodeA < N_NODES) agA = *reinterpret_cast<const float2*>(&g_agg[nodeA * D + jp]);
        if (nodeB < N_NODES) agB = *reinterpret_cast<const float2*>(&g_agg[nodeB * D + jp]);
        float m0v = fmaxf(c1[12 + nt][0] + agA.x + cb0, 0.f);
        float m1v = fmaxf(c1[12 + nt][1] + agA.y + cb1, 0.f);
        float m2v = fmaxf(c1[12 + nt][2] + agB.x + cb0, 0.f);
        float m3v = fmaxf(c1[12 + nt][3] + agB.y + cb1, 0.f);
        *reinterpret_cast<uint32_t*>(&m16[rowA * 36 + jp]) = pack_h2(m0v, m1v);
        *reinterpret_cast<uint32_t*>(&m16[rowB * 36 + jp]) = pack_h2(m2v, m3v);
    }
    __syncthreads();

    float c2[12][4];
#pragma unroll
    for (int nt = 0; nt < 12; nt++)
#pragma unroll
        for (int i = 0; i < 4; i++) c2[nt][i] = 0.f;
#pragma unroll
    for (int ks = 0; ks < 2; ks++) {
        int kb = ks * 16 + lr * 2;
        uint32_t a[4];
        a[0] = *reinterpret_cast<const uint32_t*>(&m16[(wm + lq) * 36 + kb]);
        a[2] = *reinterpret_cast<const uint32_t*>(&m16[(wm + lq) * 36 + kb + 8]);
        a[1] = *reinterpret_cast<const uint32_t*>(&m16[(wm + lq + 8) * 36 + kb]);
        a[3] = *reinterpret_cast<const uint32_t*>(&m16[(wm + lq + 8) * 36 + kb + 8]);
#pragma unroll
        for (int nt = 0; nt < 12; nt++) {
            int n = nt * 8 + lq;
            uint32_t b0 = *reinterpret_cast<const uint32_t*>(&w2[n * 36 + kb]);
            uint32_t b1 = *reinterpret_cast<const uint32_t*>(&w2[n * 36 + kb + 8]);
            mma_f16_16x8x16(c2[nt], a, b0, b1);
        }
    }

#pragma unroll
    for (int nt = 0; nt < 4; nt++) {
        int jp = nt * 8 + lr * 2;
#pragma unroll
        for (int hrow = 0; hrow < 2; hrow++) {
            int node = hrow ? nodeB : nodeA;
            if (node >= N_NODES) continue;
            int rl = hrow ? rowB : rowA;
            float hn0, hn1;
            {
                int ci = 2 * hrow;
                float gr0 = c2[nt][ci] + sbih[jp] + c1[nt][ci] + sbhh[jp];
                float gr1 = c2[nt][ci + 1] + sbih[jp + 1] + c1[nt][ci + 1] + sbhh[jp + 1];
                float gz0 = c2[4 + nt][ci] + sbih[32 + jp] + c1[4 + nt][ci] + sbhh[32 + jp];
                float gz1 = c2[4 + nt][ci + 1] + sbih[33 + jp] + c1[4 + nt][ci + 1] + sbhh[33 + jp];
                float r0 = 1.f / (1.f + expf(-gr0));
                float r1 = 1.f / (1.f + expf(-gr1));
                float z0 = 1.f / (1.f + expf(-gz0));
                float z1 = 1.f / (1.f + expf(-gz1));
                float gn0 = c2[8 + nt][ci] + sbih[64 + jp];
                float gn1 = c2[8 + nt][ci + 1] + sbih[65 + jp];
                float ghn0 = c1[8 + nt][ci] + sbhh[64 + jp];
                float ghn1 = c1[8 + nt][ci + 1] + sbhh[65 + jp];
                float n0 = tanhf(gn0 + r0 * ghn0);
                float n1 = tanhf(gn1 + r1 * ghn1);
                float hv0 = hf[rl * 36 + jp];
                float hv1 = hf[rl * 36 + jp + 1];
                hn0 = (1.f - z0) * n0 + z0 * hv0;
                hn1 = (1.f - z1) * n1 + z1 * hv1;
            }
            float2 hv2 = make_float2(hn0, hn1);
            *reinterpret_cast<float2*>(&g_h[node * D + jp]) = hv2;
            *reinterpret_cast<float2*>(&g_agg[node * D + jp]) = make_float2(0.f, 0.f);
            if (write_out)
                *reinterpret_cast<float2*>(&out[node * D + jp]) = hv2;
        }
    }
}

// ---------------- launch ----------------
extern "C" void kernel_launch(void* const* d_in, const int* in_sizes, int n_in,
                              void* d_out, int out_size) {
    (void)in_sizes; (void)n_in; (void)out_size;
    const float* x        = (const float*)d_in[0];
    const int*   ei       = (const int*)d_in[1];
    const float* ea       = (const float*)d_in[2];
    const float* proj_W   = (const float*)d_in[3];
    const float* proj_b   = (const float*)d_in[4];
    const float* bn1_g    = (const float*)d_in[5];
    const float* bn1_b    = (const float*)d_in[6];
    const float* eW1      = (const float*)d_in[7];
    const float* eb1      = (const float*)d_in[8];
    const float* bn2_g    = (const float*)d_in[9];
    const float* bn2_b    = (const float*)d_in[10];
    const float* eW2      = (const float*)d_in[11];
    const float* eb2      = (const float*)d_in[12];
    const float* root     = (const float*)d_in[13];
    const float* cb       = (const float*)d_in[14];
    const float* W_ih     = (const float*)d_in[15];
    const float* W_hh     = (const float*)d_in[16];
    const float* b_ih     = (const float*)d_in[17];
    const float* b_hh     = (const float*)d_in[18];
    float* out = (float*)d_out;

    static int attr_set = 0;
    if (!attr_set) {
        cudaFuncSetAttribute(k_theta, cudaFuncAttributeMaxDynamicSharedMemorySize,
                             TH_SMEM_TOTAL);
        cudaFuncSetAttribute(k_update, cudaFuncAttributeMaxDynamicSharedMemorySize,
                             UP_SMEM_TOTAL);
        attr_set = 1;
    }

    k_prepB<<<128, 256>>>(eW2);                                       // 1
    k_prepW<<<1, 256>>>(W_hh, root, W_ih, eW1, eb1, bn2_g, bn2_b);    // 2
    k_proj<<<N_NODES / 8, 256>>>(x, proj_W, proj_b, bn1_g, bn1_b);    // 3
    k_theta<<<N_EDGES / 128, 256, TH_SMEM_TOTAL>>>(eb2, ea);          // 4 <- profiled

    for (int s = 0; s < STEPS; s++) {
        k_msg<<<(N_EDGES * 32) / 256, 256>>>(ei);
        k_update<<<(N_NODES + 127) / 128, 256, UP_SMEM_TOTAL>>>(
            cb, b_ih, b_hh, out, s == STEPS - 1 ? 1 : 0);
    }
}